// round 14
// baseline (speedup 1.0000x reference)
#include <cuda_runtime.h>
#include <cuda_bf16.h>
#include <cstdint>
#include <cstdio>

// Problem constants
#define NN_   8192
#define T_    32
#define IN_   256
#define H_    256
#define H3_   768
#define E_    1024
#define NNZ_  65536
#define GCN_  256

// ---------------------------------------------------------------------------
// Scratch (static device globals; no runtime allocation)
// ---------------------------------------------------------------------------
__device__ float g_xgall[(size_t)NN_ * T_ * H3_];   // [t][pos][768] t-major, sorted rows
__device__ float g_h [NN_ * H_];
__device__ float g_h2[NN_ * H_];
__device__ float g_fa[NN_ * H_];                    // feature ping (last / o2)
__device__ float g_fb[NN_ * H_];                    // feature pong (o1 / o3)
__device__ float g_xw[NN_ * H_];                    // HGC x@W
__device__ float g_eb[E_ * H_];                     // HGC edge accumulator
__device__ float g_x2[NN_ * GCN_];                  // o3 @ gcn_w
__device__ unsigned char g_mask[(size_t)NN_ * NN_]; // 64 MB adjacency mask bytes
__device__ float g_deg[NN_];
__device__ float g_Dinv[NN_];
__device__ float g_Binv[E_];
__device__ float g_dis[NN_];
// bf16 pre-split buffers
__device__ __nv_bfloat16 g_whh_h[H3_ * H_];
__device__ __nv_bfloat16 g_whh_l[H3_ * H_];
__device__ __nv_bfloat16 g_wih_h[H3_ * IN_];
__device__ __nv_bfloat16 g_wih_l[H3_ * IN_];
__device__ __nv_bfloat16 g_o3h[NN_ * H_];
__device__ __nv_bfloat16 g_o3l[NN_ * H_];
__device__ __nv_bfloat16 g_yth[(size_t)GCN_ * NN_];
__device__ __nv_bfloat16 g_ytl[(size_t)GCN_ * NN_];
__device__ __nv_bfloat16 g_wt_h[4 * H_ * H_];       // w1,w2,w3,gcn_w transposed+split
__device__ __nv_bfloat16 g_wt_l[4 * H_ * H_];
// sequence-length sort
__device__ int g_perm[NN_];
__device__ int g_hist[32];
__device__ int g_cur[32];
__device__ int g_start[32];
__device__ int g_cnt[T_ + 1];
// nnz segment sort (by edge, by node)
__device__ int g_ecnt[E_];
__device__ int g_ncnt[NN_];
__device__ int g_ecur[E_];
__device__ int g_ncur[NN_];
__device__ int g_eoff[E_ + 1];
__device__ int g_noff[NN_ + 1];
__device__ int g_eorder[NNZ_];
__device__ int g_norder[NNZ_];

// ---------------------------------------------------------------------------
// helpers
// ---------------------------------------------------------------------------
__device__ __forceinline__ float sigf(float x)
{
    return 1.f / (1.f + __expf(-x));
}

__device__ __forceinline__ uint32_t cvta_smem(const void* p)
{
    uint32_t a;
    asm("{ .reg .u64 t; cvta.to.shared.u64 t, %1; cvt.u32.u64 %0, t; }"
        : "=r"(a) : "l"(p));
    return a;
}

__device__ __forceinline__ void cpa16(uint32_t dst, const void* src)
{
    asm volatile("cp.async.cg.shared.global [%0], [%1], 16;"
                 :: "r"(dst), "l"(src) : "memory");
}

#define CP_COMMIT() asm volatile("cp.async.commit_group;" ::: "memory")
#define CP_WAIT1()  asm volatile("cp.async.wait_group 1;" ::: "memory")
#define CP_WAIT0()  asm volatile("cp.async.wait_group 0;" ::: "memory")

__device__ __forceinline__ void split8(const float* __restrict__ s, uint4& hi, uint4& lo)
{
    float4 v0 = *(const float4*)s;
    float4 v1 = *(const float4*)(s + 4);
    float vv[8] = {v0.x, v0.y, v0.z, v0.w, v1.x, v1.y, v1.z, v1.w};
    unsigned hw[4], lw[4];
#pragma unroll
    for (int p = 0; p < 4; p++) {
        __nv_bfloat16 h0 = __float2bfloat16(vv[2 * p]);
        __nv_bfloat16 h1 = __float2bfloat16(vv[2 * p + 1]);
        __nv_bfloat16 l0 = __float2bfloat16(vv[2 * p] - __bfloat162float(h0));
        __nv_bfloat16 l1 = __float2bfloat16(vv[2 * p + 1] - __bfloat162float(h1));
        __nv_bfloat162 hp = __halves2bfloat162(h0, h1);
        __nv_bfloat162 lp = __halves2bfloat162(l0, l1);
        hw[p] = *(unsigned*)&hp;
        lw[p] = *(unsigned*)&lp;
    }
    hi = make_uint4(hw[0], hw[1], hw[2], hw[3]);
    lo = make_uint4(lw[0], lw[1], lw[2], lw[3]);
}

__device__ __forceinline__ void mma_bf16(float* c, const uint32_t* a, const uint32_t* b)
{
    asm volatile(
        "mma.sync.aligned.m16n8k16.row.col.f32.bf16.bf16.f32 "
        "{%0,%1,%2,%3}, {%4,%5,%6,%7}, {%8,%9}, {%0,%1,%2,%3};"
        : "+f"(c[0]), "+f"(c[1]), "+f"(c[2]), "+f"(c[3])
        : "r"(a[0]), "r"(a[1]), "r"(a[2]), "r"(a[3]), "r"(b[0]), "r"(b[1]));
}

// ---------------------------------------------------------------------------
// One-time split kernels
// ---------------------------------------------------------------------------
__global__ void split_w_kernel(const float* __restrict__ W,
                               __nv_bfloat16* __restrict__ Wh,
                               __nv_bfloat16* __restrict__ Wl, int n)
{
    int i = blockIdx.x * 256 + threadIdx.x;
    if (i < n) {
        float v = W[i];
        __nv_bfloat16 h = __float2bfloat16(v);
        Wh[i] = h;
        Wl[i] = __float2bfloat16(v - __bfloat162float(h));
    }
}

// Transpose + split a [K=256][N=256] weight -> [n][k] bf16 hi/lo.
__global__ void wt_split_kernel(const float* __restrict__ W,
                                __nv_bfloat16* __restrict__ Wth,
                                __nv_bfloat16* __restrict__ Wtl)
{
    __shared__ float tile[32][33];
    int kb = blockIdx.x * 32;
    int nb = blockIdx.y * 32;
    int tx = threadIdx.x, ty = threadIdx.y;
    for (int i = ty; i < 32; i += 8)
        tile[i][tx] = W[(size_t)(kb + i) * H_ + nb + tx];
    __syncthreads();
    for (int i = ty; i < 32; i += 8) {
        float v = tile[tx][i];
        __nv_bfloat16 h = __float2bfloat16(v);
        Wth[(size_t)(nb + i) * H_ + kb + tx] = h;
        Wtl[(size_t)(nb + i) * H_ + kb + tx] = __float2bfloat16(v - __bfloat162float(h));
    }
}

// Y^T build: Yt[n][k] = dis[k] * x2[k][n], split hi/lo bf16.
__global__ void yt_split_kernel(const float* __restrict__ x2,
                                const float* __restrict__ dis,
                                __nv_bfloat16* __restrict__ Yth,
                                __nv_bfloat16* __restrict__ Ytl)
{
    __shared__ float tile[32][33];
    int kb = blockIdx.x * 32;
    int nb = blockIdx.y * 32;
    int tx = threadIdx.x, ty = threadIdx.y;
    for (int i = ty; i < 32; i += 8)
        tile[i][tx] = x2[(size_t)(kb + i) * GCN_ + nb + tx] * dis[kb + i];
    __syncthreads();
    for (int i = ty; i < 32; i += 8) {
        float v = tile[tx][i];
        __nv_bfloat16 h = __float2bfloat16(v);
        Yth[(size_t)(nb + i) * NN_ + kb + tx] = h;
        Ytl[(size_t)(nb + i) * NN_ + kb + tx] = __float2bfloat16(v - __bfloat162float(h));
    }
}

// ---------------------------------------------------------------------------
// Tensor-core input-gate GEMM (round-10 proven).
// ---------------------------------------------------------------------------
#define XS_ 88
__global__ __launch_bounds__(256, 2)
void xg_gemm_mma(const float* __restrict__ x,
                 const __nv_bfloat16* __restrict__ Wih_h,
                 const __nv_bfloat16* __restrict__ Wih_l,
                 const float* __restrict__ bih,
                 const int* __restrict__ perm,
                 const int* __restrict__ cnt,
                 float* __restrict__ xgall)
{
    const int bm = blockIdx.y * 128;
    const int t = bm >> 13;
    const int pos0 = bm & (NN_ - 1);
    if (pos0 >= cnt[t]) return;
    const int bn = blockIdx.x * 128;

    extern __shared__ __align__(16) __nv_bfloat16 smx[];
    __nv_bfloat16* Ah = smx;
    __nv_bfloat16* Al = smx + 128 * XS_;
    __nv_bfloat16* Bh = smx + 2 * 128 * XS_;
    __nv_bfloat16* Bl = smx + 3 * 128 * XS_;

    const int tid = threadIdx.x;
    const int wid = tid >> 5;
    const int lane = tid & 31;
    const int wm = (wid & 3) * 32;
    const int wn = (wid >> 2) * 64;
    const int grp = lane >> 2;
    const int tig = lane & 3;

    float acc[2][8][4];
#pragma unroll
    for (int mt = 0; mt < 2; mt++)
#pragma unroll
        for (int nt = 0; nt < 8; nt++)
#pragma unroll
            for (int e = 0; e < 4; e++) acc[mt][nt][e] = 0.f;

    for (int kc = 0; kc < 4; kc++) {
#pragma unroll
        for (int i = 0; i < 4; i++) {
            int u = i * 256 + tid;
            int r = u >> 3;
            int cg = u & 7;
            uint4 hi, lo;
            split8(x + (size_t)perm[pos0 + r] * (T_ * IN_) + t * IN_ + kc * 64 + cg * 8,
                   hi, lo);
            *(uint4*)(Ah + r * XS_ + cg * 8) = hi;
            *(uint4*)(Al + r * XS_ + cg * 8) = lo;
        }
#pragma unroll
        for (int i = 0; i < 4; i++) {
            int u = i * 256 + tid;
            int r = u >> 3;
            int cg = u & 7;
            size_t goff = (size_t)(bn + r) * IN_ + kc * 64 + cg * 8;
            *(uint4*)(Bh + r * XS_ + cg * 8) = *(const uint4*)(Wih_h + goff);
            *(uint4*)(Bl + r * XS_ + cg * 8) = *(const uint4*)(Wih_l + goff);
        }
        __syncthreads();

#pragma unroll
        for (int ks = 0; ks < 4; ks++) {
            const int kk = ks * 16;
            uint32_t ah[2][4], al[2][4];
#pragma unroll
            for (int mt = 0; mt < 2; mt++) {
                int r0 = wm + mt * 16 + grp;
                ah[mt][0] = *(const uint32_t*)(Ah + (size_t)r0 * XS_ + kk + tig * 2);
                ah[mt][1] = *(const uint32_t*)(Ah + (size_t)(r0 + 8) * XS_ + kk + tig * 2);
                ah[mt][2] = *(const uint32_t*)(Ah + (size_t)r0 * XS_ + kk + 8 + tig * 2);
                ah[mt][3] = *(const uint32_t*)(Ah + (size_t)(r0 + 8) * XS_ + kk + 8 + tig * 2);
                al[mt][0] = *(const uint32_t*)(Al + (size_t)r0 * XS_ + kk + tig * 2);
                al[mt][1] = *(const uint32_t*)(Al + (size_t)(r0 + 8) * XS_ + kk + tig * 2);
                al[mt][2] = *(const uint32_t*)(Al + (size_t)r0 * XS_ + kk + 8 + tig * 2);
                al[mt][3] = *(const uint32_t*)(Al + (size_t)(r0 + 8) * XS_ + kk + 8 + tig * 2);
            }
#pragma unroll
            for (int nt = 0; nt < 8; nt++) {
                int nr = wn + nt * 8 + grp;
                uint32_t bh[2], bl[2];
                bh[0] = *(const uint32_t*)(Bh + (size_t)nr * XS_ + kk + tig * 2);
                bh[1] = *(const uint32_t*)(Bh + (size_t)nr * XS_ + kk + 8 + tig * 2);
                bl[0] = *(const uint32_t*)(Bl + (size_t)nr * XS_ + kk + tig * 2);
                bl[1] = *(const uint32_t*)(Bl + (size_t)nr * XS_ + kk + 8 + tig * 2);
#pragma unroll
                for (int mt = 0; mt < 2; mt++) {
                    mma_bf16(acc[mt][nt], ah[mt], bh);
                    mma_bf16(acc[mt][nt], ah[mt], bl);
                    mma_bf16(acc[mt][nt], al[mt], bh);
                }
            }
        }
        __syncthreads();
    }

#pragma unroll
    for (int mt = 0; mt < 2; mt++) {
#pragma unroll
        for (int nt = 0; nt < 8; nt++) {
            int row0 = bm + wm + mt * 16 + grp;
            int col = bn + wn + nt * 8 + tig * 2;
            float2 bv = *(const float2*)(bih + col);
            float2 o0 = make_float2(acc[mt][nt][0] + bv.x, acc[mt][nt][1] + bv.y);
            float2 o1 = make_float2(acc[mt][nt][2] + bv.x, acc[mt][nt][3] + bv.y);
            *(float2*)(xgall + (size_t)row0 * H3_ + col) = o0;
            *(float2*)(xgall + (size_t)(row0 + 8) * H3_ + col) = o1;
        }
    }
}

// ---------------------------------------------------------------------------
// Fused GRU step (round-13 champion + cp.async double-buffered W_hh prefetch).
// smem: A hi/lo (single buffer) + B hi/lo (double buffer) = 129024 B.
// ---------------------------------------------------------------------------
#define GS_ 72
#define GBB_ (192 * GS_)
__global__ __launch_bounds__(256)
void gru_step_mma(const __nv_bfloat16* __restrict__ Whh_h,
                  const __nv_bfloat16* __restrict__ Whh_l,
                  const float* __restrict__ bhh,
                  const float* __restrict__ xgall,
                  const float* __restrict__ hin,
                  float* __restrict__ hout,
                  const int* __restrict__ perm,
                  const int* __restrict__ cnt,
                  float* __restrict__ last, int t)
{
    const int bm = blockIdx.y * 64;
    const int c0 = cnt[t];
    if (bm >= c0) return;
    const int c1 = cnt[t + 1];
    const int bn = blockIdx.x * 64;

    extern __shared__ __align__(16) __nv_bfloat16 smg[];
    __nv_bfloat16* Ah  = smg;                       // [64][GS_]
    __nv_bfloat16* Al  = smg + 64 * GS_;
    __nv_bfloat16* Bh0 = smg + 2 * 64 * GS_;        // [2][192][GS_]
    __nv_bfloat16* Bl0 = Bh0 + 2 * GBB_;            // [2][192][GS_]

    const int tid = threadIdx.x;
    const int wid = tid >> 5;
    const int lane = tid & 31;
    const int wm = (wid & 1) * 32;
    const int wn16 = (wid >> 1) * 16;
    const int grp = lane >> 2;
    const int tig = lane & 3;

    // per-thread B-copy geometry (constant across chunks)
    const int br_r  = tid >> 3;          // base row for i=0 (0..31); +32 per i
    const int br_cg = tid & 7;

    float acc[2][3][2][4];
#pragma unroll
    for (int mt = 0; mt < 2; mt++)
#pragma unroll
        for (int g = 0; g < 3; g++)
#pragma unroll
            for (int nt = 0; nt < 2; nt++)
#pragma unroll
                for (int e = 0; e < 4; e++) acc[mt][g][nt][e] = 0.f;

    // ---- issue B chunk 0 prefetch ----
    {
        uint32_t bhA = cvta_smem(Bh0);
        uint32_t blA = cvta_smem(Bl0);
#pragma unroll
        for (int i = 0; i < 6; i++) {
            int r = br_r + i * 32;
            int g = r >> 6;
            int brr = r & 63;
            size_t goff = (size_t)(g * 256 + bn + brr) * H_ + br_cg * 8;
            uint32_t soff = (uint32_t)(r * GS_ + br_cg * 8) * 2;
            cpa16(bhA + soff, Whh_h + goff);
            cpa16(blA + soff, Whh_l + goff);
        }
        CP_COMMIT();
    }

    for (int kc = 0; kc < 4; kc++) {
        const int cur = kc & 1;
        // A: split hin chunk kc (A buffer free after previous trailing sync)
#pragma unroll
        for (int i = 0; i < 2; i++) {
            int u = i * 256 + tid;
            int r = u >> 3;
            int cg = u & 7;
            uint4 hi, lo;
            split8(hin + (size_t)(bm + r) * H_ + kc * 64 + cg * 8, hi, lo);
            *(uint4*)(Ah + r * GS_ + cg * 8) = hi;
            *(uint4*)(Al + r * GS_ + cg * 8) = lo;
        }
        // prefetch B chunk kc+1 into the other buffer
        if (kc < 3) {
            uint32_t bhA = cvta_smem(Bh0 + ((kc + 1) & 1) * GBB_);
            uint32_t blA = cvta_smem(Bl0 + ((kc + 1) & 1) * GBB_);
#pragma unroll
            for (int i = 0; i < 6; i++) {
                int r = br_r + i * 32;
                int g = r >> 6;
                int brr = r & 63;
                size_t goff = (size_t)(g * 256 + bn + brr) * H_ + (kc + 1) * 64 + br_cg * 8;
                uint32_t soff = (uint32_t)(r * GS_ + br_cg * 8) * 2;
                cpa16(bhA + soff, Whh_h + goff);
                cpa16(blA + soff, Whh_l + goff);
            }
            CP_COMMIT();
            CP_WAIT1();          // chunk kc's group complete
        } else {
            CP_WAIT0();
        }
        __syncthreads();

        const __nv_bfloat16* Bh = Bh0 + cur * GBB_;
        const __nv_bfloat16* Bl = Bl0 + cur * GBB_;

#pragma unroll
        for (int ks = 0; ks < 4; ks++) {
            const int kk = ks * 16;
            uint32_t ah[2][4], al[2][4];
#pragma unroll
            for (int mt = 0; mt < 2; mt++) {
                int r0 = wm + mt * 16 + grp;
                ah[mt][0] = *(const uint32_t*)(Ah + (size_t)r0 * GS_ + kk + tig * 2);
                ah[mt][1] = *(const uint32_t*)(Ah + (size_t)(r0 + 8) * GS_ + kk + tig * 2);
                ah[mt][2] = *(const uint32_t*)(Ah + (size_t)r0 * GS_ + kk + 8 + tig * 2);
                ah[mt][3] = *(const uint32_t*)(Ah + (size_t)(r0 + 8) * GS_ + kk + 8 + tig * 2);
                al[mt][0] = *(const uint32_t*)(Al + (size_t)r0 * GS_ + kk + tig * 2);
                al[mt][1] = *(const uint32_t*)(Al + (size_t)(r0 + 8) * GS_ + kk + tig * 2);
                al[mt][2] = *(const uint32_t*)(Al + (size_t)r0 * GS_ + kk + 8 + tig * 2);
                al[mt][3] = *(const uint32_t*)(Al + (size_t)(r0 + 8) * GS_ + kk + 8 + tig * 2);
            }
#pragma unroll
            for (int g = 0; g < 3; g++) {
#pragma unroll
                for (int nt = 0; nt < 2; nt++) {
                    int nr = g * 64 + wn16 + nt * 8 + grp;
                    uint32_t bh[2], bl[2];
                    bh[0] = *(const uint32_t*)(Bh + (size_t)nr * GS_ + kk + tig * 2);
                    bh[1] = *(const uint32_t*)(Bh + (size_t)nr * GS_ + kk + 8 + tig * 2);
                    bl[0] = *(const uint32_t*)(Bl + (size_t)nr * GS_ + kk + tig * 2);
                    bl[1] = *(const uint32_t*)(Bl + (size_t)nr * GS_ + kk + 8 + tig * 2);
#pragma unroll
                    for (int mt = 0; mt < 2; mt++) {
                        mma_bf16(acc[mt][g][nt], ah[mt], bh);
                        mma_bf16(acc[mt][g][nt], ah[mt], bl);
                        mma_bf16(acc[mt][g][nt], al[mt], bh);
                    }
                }
            }
        }
        __syncthreads();
    }

#pragma unroll
    for (int mt = 0; mt < 2; mt++) {
        int rbase = bm + wm + mt * 16 + grp;
#pragma unroll
        for (int half = 0; half < 2; half++) {
            int row = rbase + half * 8;
            bool isLast = (row >= c1 && row < c0);
            int pr = isLast ? perm[row] : 0;
            size_t xb = ((size_t)t * NN_ + row) * H3_;
            size_t hb = (size_t)row * H_;
#pragma unroll
            for (int nt = 0; nt < 2; nt++) {
                int col = bn + wn16 + nt * 8 + tig * 2;
                float2 xr = *(const float2*)(xgall + xb + col);
                float2 xz = *(const float2*)(xgall + xb + 256 + col);
                float2 xq = *(const float2*)(xgall + xb + 512 + col);
                float2 ho = *(const float2*)(hin + hb + col);
                float2 br = *(const float2*)(bhh + col);
                float2 bz = *(const float2*)(bhh + 256 + col);
                float2 bq = *(const float2*)(bhh + 512 + col);
                float hr0 = acc[mt][0][nt][half * 2 + 0];
                float hr1 = acc[mt][0][nt][half * 2 + 1];
                float hz0 = acc[mt][1][nt][half * 2 + 0];
                float hz1 = acc[mt][1][nt][half * 2 + 1];
                float hq0 = acc[mt][2][nt][half * 2 + 0];
                float hq1 = acc[mt][2][nt][half * 2 + 1];
                float r0 = sigf(xr.x + hr0 + br.x);
                float z0 = sigf(xz.x + hz0 + bz.x);
                float q0 = tanhf(xq.x + r0 * (hq0 + bq.x));
                float r1 = sigf(xr.y + hr1 + br.y);
                float z1 = sigf(xz.y + hz1 + bz.y);
                float q1 = tanhf(xq.y + r1 * (hq1 + bq.y));
                float2 hn = make_float2((1.f - z0) * q0 + z0 * ho.x,
                                        (1.f - z1) * q1 + z1 * ho.y);
                *(float2*)(hout + hb + col) = hn;
                if (isLast)
                    *(float2*)(last + (size_t)pr * H_ + col) = hn;
            }
        }
    }
}

// ---------------------------------------------------------------------------
// HMMA NT GEMM (round-8 proven): C[M,256] = A (fp32 split) @ Wt (pre-split).
// ---------------------------------------------------------------------------
__global__ __launch_bounds__(256, 2)
void sgemm_nt_mma(const float* __restrict__ A,
                  const __nv_bfloat16* __restrict__ Wth,
                  const __nv_bfloat16* __restrict__ Wtl,
                  float* __restrict__ C)
{
    const int bm = blockIdx.y * 128;
    const int bn = blockIdx.x * 128;

    extern __shared__ __align__(16) __nv_bfloat16 smn[];
    __nv_bfloat16* Ah = smn;
    __nv_bfloat16* Al = smn + 128 * XS_;
    __nv_bfloat16* Bh = smn + 2 * 128 * XS_;
    __nv_bfloat16* Bl = smn + 3 * 128 * XS_;

    const int tid = threadIdx.x;
    const int wid = tid >> 5;
    const int lane = tid & 31;
    const int wm = (wid & 3) * 32;
    const int wn = (wid >> 2) * 64;
    const int grp = lane >> 2;
    const int tig = lane & 3;

    float acc[2][8][4];
#pragma unroll
    for (int mt = 0; mt < 2; mt++)
#pragma unroll
        for (int nt = 0; nt < 8; nt++)
#pragma unroll
            for (int e = 0; e < 4; e++) acc[mt][nt][e] = 0.f;

    for (int kc = 0; kc < 4; kc++) {
#pragma unroll
        for (int i = 0; i < 4; i++) {
            int u = i * 256 + tid;
            int r = u >> 3;
            int cg = u & 7;
            uint4 hi, lo;
            split8(A + (size_t)(bm + r) * H_ + kc * 64 + cg * 8, hi, lo);
            *(uint4*)(Ah + r * XS_ + cg * 8) = hi;
            *(uint4*)(Al + r * XS_ + cg * 8) = lo;
        }
#pragma unroll
        for (int i = 0; i < 4; i++) {
            int u = i * 256 + tid;
            int r = u >> 3;
            int cg = u & 7;
            size_t goff = (size_t)(bn + r) * H_ + kc * 64 + cg * 8;
            *(uint4*)(Bh + r * XS_ + cg * 8) = *(const uint4*)(Wth + goff);
            *(uint4*)(Bl + r * XS_ + cg * 8) = *(const uint4*)(Wtl + goff);
        }
        __syncthreads();

#pragma unroll
        for (int ks = 0; ks < 4; ks++) {
            const int kk = ks * 16;
            uint32_t ah[2][4], al[2][4];
#pragma unroll
            for (int mt = 0; mt < 2; mt++) {
                int r0 = wm + mt * 16 + grp;
                ah[mt][0] = *(const uint32_t*)(Ah + (size_t)r0 * XS_ + kk + tig * 2);
                ah[mt][1] = *(const uint32_t*)(Ah + (size_t)(r0 + 8) * XS_ + kk + tig * 2);
                ah[mt][2] = *(const uint32_t*)(Ah + (size_t)r0 * XS_ + kk + 8 + tig * 2);
                ah[mt][3] = *(const uint32_t*)(Ah + (size_t)(r0 + 8) * XS_ + kk + 8 + tig * 2);
                al[mt][0] = *(const uint32_t*)(Al + (size_t)r0 * XS_ + kk + tig * 2);
                al[mt][1] = *(const uint32_t*)(Al + (size_t)(r0 + 8) * XS_ + kk + tig * 2);
                al[mt][2] = *(const uint32_t*)(Al + (size_t)r0 * XS_ + kk + 8 + tig * 2);
                al[mt][3] = *(const uint32_t*)(Al + (size_t)(r0 + 8) * XS_ + kk + 8 + tig * 2);
            }
#pragma unroll
            for (int nt = 0; nt < 8; nt++) {
                int nr = wn + nt * 8 + grp;
                uint32_t bh[2], bl[2];
                bh[0] = *(const uint32_t*)(Bh + (size_t)nr * XS_ + kk + tig * 2);
                bh[1] = *(const uint32_t*)(Bh + (size_t)nr * XS_ + kk + 8 + tig * 2);
                bl[0] = *(const uint32_t*)(Bl + (size_t)nr * XS_ + kk + tig * 2);
                bl[1] = *(const uint32_t*)(Bl + (size_t)nr * XS_ + kk + 8 + tig * 2);
#pragma unroll
                for (int mt = 0; mt < 2; mt++) {
                    mma_bf16(acc[mt][nt], ah[mt], bh);
                    mma_bf16(acc[mt][nt], ah[mt], bl);
                    mma_bf16(acc[mt][nt], al[mt], bh);
                }
            }
        }
        __syncthreads();
    }

#pragma unroll
    for (int mt = 0; mt < 2; mt++) {
#pragma unroll
        for (int nt = 0; nt < 8; nt++) {
            int row0 = bm + wm + mt * 16 + grp;
            int col = bn + wn + nt * 8 + tig * 2;
            *(float2*)(C + (size_t)row0 * H_ + col) =
                make_float2(acc[mt][nt][0], acc[mt][nt][1]);
            *(float2*)(C + (size_t)(row0 + 8) * H_ + col) =
                make_float2(acc[mt][nt][2], acc[mt][nt][3]);
        }
    }
}

// ---------------------------------------------------------------------------
// Gram -> mask + deg (round-10 proven, pre-split o3).
// ---------------------------------------------------------------------------
__global__ __launch_bounds__(256)
void gram_mma(const __nv_bfloat16* __restrict__ Xh,
              const __nv_bfloat16* __restrict__ Xl,
              unsigned char* __restrict__ mask,
              float* __restrict__ deg,
              const float* __restrict__ phi_p)
{
    int k = blockIdx.x;
    int bi = 0;
    while (k >= 64 - bi) { k -= 64 - bi; bi++; }
    const int bj = bi + k;
    const int bm = bi * 128;
    const int bn = bj * 128;

    extern __shared__ __align__(16) __nv_bfloat16 smr[];
    __nv_bfloat16* Ah = smr;
    __nv_bfloat16* Al = smr + 128 * XS_;
    __nv_bfloat16* Bh = smr + 2 * 128 * XS_;
    __nv_bfloat16* Bl = smr + 3 * 128 * XS_;

    const int tid = threadIdx.x;
    const int wid = tid >> 5;
    const int lane = tid & 31;
    const int wm = (wid & 3) * 32;
    const int wn = (wid >> 2) * 64;
    const int grp = lane >> 2;
    const int tig = lane & 3;

    float acc[2][8][4];
#pragma unroll
    for (int mt = 0; mt < 2; mt++)
#pragma unroll
        for (int nt = 0; nt < 8; nt++)
#pragma unroll
            for (int e = 0; e < 4; e++) acc[mt][nt][e] = 0.f;

    for (int kc = 0; kc < 4; kc++) {
#pragma unroll
        for (int i = 0; i < 8; i++) {
            int u = i * 256 + tid;
            int r = u >> 3;
            int cg = u & 7;
            int grow = (r < 128) ? (bm + r) : (bn + r - 128);
            int lr = r & 127;
            __nv_bfloat16* dh = (r < 128) ? Ah : Bh;
            __nv_bfloat16* dl = (r < 128) ? Al : Bl;
            size_t goff = (size_t)grow * H_ + kc * 64 + cg * 8;
            *(uint4*)(dh + lr * XS_ + cg * 8) = *(const uint4*)(Xh + goff);
            *(uint4*)(dl + lr * XS_ + cg * 8) = *(const uint4*)(Xl + goff);
        }
        __syncthreads();

#pragma unroll
        for (int ks = 0; ks < 4; ks++) {
            const int kk = ks * 16;
            uint32_t ah[2][4], al[2][4];
#pragma unroll
            for (int mt = 0; mt < 2; mt++) {
                int r0 = wm + mt * 16 + grp;
                ah[mt][0] = *(const uint32_t*)(Ah + (size_t)r0 * XS_ + kk + tig * 2);
                ah[mt][1] = *(const uint32_t*)(Ah + (size_t)(r0 + 8) * XS_ + kk + tig * 2);
                ah[mt][2] = *(const uint32_t*)(Ah + (size_t)r0 * XS_ + kk + 8 + tig * 2);
                ah[mt][3] = *(const uint32_t*)(Ah + (size_t)(r0 + 8) * XS_ + kk + 8 + tig * 2);
                al[mt][0] = *(const uint32_t*)(Al + (size_t)r0 * XS_ + kk + tig * 2);
                al[mt][1] = *(const uint32_t*)(Al + (size_t)(r0 + 8) * XS_ + kk + tig * 2);
                al[mt][2] = *(const uint32_t*)(Al + (size_t)r0 * XS_ + kk + 8 + tig * 2);
                al[mt][3] = *(const uint32_t*)(Al + (size_t)(r0 + 8) * XS_ + kk + 8 + tig * 2);
            }
#pragma unroll
            for (int nt = 0; nt < 8; nt++) {
                int nr = wn + nt * 8 + grp;
                uint32_t bh[2], bl[2];
                bh[0] = *(const uint32_t*)(Bh + (size_t)nr * XS_ + kk + tig * 2);
                bh[1] = *(const uint32_t*)(Bh + (size_t)nr * XS_ + kk + 8 + tig * 2);
                bl[0] = *(const uint32_t*)(Bl + (size_t)nr * XS_ + kk + tig * 2);
                bl[1] = *(const uint32_t*)(Bl + (size_t)nr * XS_ + kk + 8 + tig * 2);
#pragma unroll
                for (int mt = 0; mt < 2; mt++) {
                    mma_bf16(acc[mt][nt], ah[mt], bh);
                    mma_bf16(acc[mt][nt], ah[mt], bl);
                    mma_bf16(acc[mt][nt], al[mt], bh);
                }
            }
        }
        __syncthreads();
    }

    const float thr = phi_p[0] * 65536.0f;
    float cnt_r[2][2] = {{0.f, 0.f}, {0.f, 0.f}};
    float cnt_c[8][2];
#pragma unroll
    for (int nt = 0; nt < 8; nt++) { cnt_c[nt][0] = 0.f; cnt_c[nt][1] = 0.f; }
    unsigned bits[2][8];

#pragma unroll
    for (int mt = 0; mt < 2; mt++) {
        int r0 = bm + wm + mt * 16 + grp;
#pragma unroll
        for (int nt = 0; nt < 8; nt++) {
            int c0 = bn + wn + nt * 8 + tig * 2;
            unsigned b00 = (acc[mt][nt][0] >= thr || r0 == c0) ? 1u : 0u;
            unsigned b01 = (acc[mt][nt][1] >= thr || r0 == c0 + 1) ? 1u : 0u;
            unsigned b10 = (acc[mt][nt][2] >= thr || r0 + 8 == c0) ? 1u : 0u;
            unsigned b11 = (acc[mt][nt][3] >= thr || r0 + 8 == c0 + 1) ? 1u : 0u;
            *(unsigned short*)(mask + (size_t)r0 * NN_ + c0) =
                (unsigned short)(b00 | (b01 << 8));
            *(unsigned short*)(mask + (size_t)(r0 + 8) * NN_ + c0) =
                (unsigned short)(b10 | (b11 << 8));
            cnt_r[mt][0] += (float)(b00 + b01);
            cnt_r[mt][1] += (float)(b10 + b11);
            cnt_c[nt][0] += (float)(b00 + b10);
            cnt_c[nt][1] += (float)(b01 + b11);
            bits[mt][nt] = b00 | (b01 << 1) | (b10 << 2) | (b11 << 3);
        }
    }

#pragma unroll
    for (int mt = 0; mt < 2; mt++)
#pragma unroll
        for (int half = 0; half < 2; half++) {
            float v = cnt_r[mt][half];
            v += __shfl_xor_sync(0xffffffffu, v, 1);
            v += __shfl_xor_sync(0xffffffffu, v, 2);
            if (tig == 0)
                atomicAdd(&deg[bm + wm + mt * 16 + grp + half * 8], v);
        }

    if (bi != bj) {
#pragma unroll
        for (int nt = 0; nt < 8; nt++)
#pragma unroll
            for (int cb = 0; cb < 2; cb++) {
                float v = cnt_c[nt][cb];
                v += __shfl_xor_sync(0xffffffffu, v, 4);
                v += __shfl_xor_sync(0xffffffffu, v, 8);
                v += __shfl_xor_sync(0xffffffffu, v, 16);
                if (grp == 0)
                    atomicAdd(&deg[bn + wn + nt * 8 + tig * 2 + cb], v);
            }
#pragma unroll
        for (int nt = 0; nt < 8; nt++) {
            int c0 = bn + wn + nt * 8 + tig * 2;
#pragma unroll
            for (int cb = 0; cb < 2; cb++) {
                int col = c0 + cb;
#pragma unroll
                for (int mt = 0; mt < 2; mt++) {
                    int r0 = bm + wm + mt * 16 + grp;
                    mask[(size_t)col * NN_ + r0] =
                        (unsigned char)((bits[mt][nt] >> cb) & 1u);
                    mask[(size_t)col * NN_ + r0 + 8] =
                        (unsigned char)((bits[mt][nt] >> (2 + cb)) & 1u);
                }
            }
        }
    }
}

// ---------------------------------------------------------------------------
// Masked GCN GEMM (round-8 proven)
// ---------------------------------------------------------------------------
#define CS_ 72
__global__ __launch_bounds__(256, 2)
void gcn_gemm_mma(const unsigned char* __restrict__ mask,
                  const __nv_bfloat16* __restrict__ Yth,
                  const __nv_bfloat16* __restrict__ Ytl,
                  const float* __restrict__ dis,
                  const float* __restrict__ bias,
                  float* __restrict__ out)
{
    __shared__ __align__(16) __nv_bfloat16 Am[128 * CS_];
    __shared__ __align__(16) __nv_bfloat16 Bh[64 * CS_];
    __shared__ __align__(16) __nv_bfloat16 Bl[64 * CS_];

    const int bm = blockIdx.y * 128;
    const int bn = blockIdx.x * 64;
    const int tid = threadIdx.x;
    const int wid = tid >> 5;
    const int lane = tid & 31;
    const int wm = (wid & 3) * 32;
    const int wn = (wid >> 2) * 32;
    const int grp = lane >> 2;
    const int tig = lane & 3;

    float acc[2][4][4];
#pragma unroll
    for (int mt = 0; mt < 2; mt++)
#pragma unroll
        for (int nt = 0; nt < 4; nt++)
#pragma unroll
            for (int e = 0; e < 4; e++) acc[mt][nt][e] = 0.f;

    for (int kc = 0; kc < NN_ / 64; kc++) {
#pragma unroll
        for (int i = 0; i < 4; i++) {
            int u = i * 256 + tid;
            int r = u >> 3;
            int cg = u & 7;
            unsigned long long mb = *(const unsigned long long*)(
                mask + (size_t)(bm + r) * NN_ + kc * 64 + cg * 8);
            unsigned w[4];
#pragma unroll
            for (int p = 0; p < 4; p++) {
                unsigned lo16 = ((mb >> (16 * p)) & 0xFFull) ? 0x3F80u : 0u;
                unsigned hi16 = ((mb >> (16 * p + 8)) & 0xFFull) ? 0x3F80u : 0u;
                w[p] = lo16 | (hi16 << 16);
            }
            *(uint4*)(Am + r * CS_ + cg * 8) = make_uint4(w[0], w[1], w[2], w[3]);
        }
#pragma unroll
        for (int i = 0; i < 2; i++) {
            int u = i * 256 + tid;
            int r = u >> 3;
            int cg = u & 7;
            size_t goff = (size_t)(bn + r) * NN_ + kc * 64 + cg * 8;
            *(uint4*)(Bh + r * CS_ + cg * 8) = *(const uint4*)(Yth + goff);
            *(uint4*)(Bl + r * CS_ + cg * 8) = *(const uint4*)(Ytl + goff);
        }
        __syncthreads();

#pragma unroll
        for (int ks = 0; ks < 4; ks++) {
            const int kk = ks * 16;
            uint32_t am[2][4];
#pragma unroll
            for (int mt = 0; mt < 2; mt++) {
                int r0 = wm + mt * 16 + grp;
                am[mt][0] = *(const uint32_t*)(Am + (size_t)r0 * CS_ + kk + tig * 2);
                am[mt][1] = *(const uint32_t*)(Am + (size_t)(r0 + 8) * CS_ + kk + tig * 2);
                am[mt][2] = *(const uint32_t*)(Am + (size_t)r0 * CS_ + kk + 8 + tig * 2);
                am[mt][3] = *(const uint32_t*)(Am + (size_t)(r0 + 8) * CS_ + kk + 8 + tig * 2);
            }
#pragma unroll
            for (int nt = 0; nt < 4; nt++) {
                int nr = wn + nt * 8 + grp;
                uint32_t bh[2], bl[2];
                bh[0] = *(const uint32_t*)(Bh + (size_t)nr * CS_ + kk + tig * 2);
                bh[1] = *(const uint32_t*)(Bh + (size_t)nr * CS_ + kk + 8 + tig * 2);
                bl[0] = *(const uint32_t*)(Bl + (size_t)nr * CS_ + kk + tig * 2);
                bl[1] = *(const uint32_t*)(Bl + (size_t)nr * CS_ + kk + 8 + tig * 2);
#pragma unroll
                for (int mt = 0; mt < 2; mt++) {
                    mma_bf16(acc[mt][nt], am[mt], bh);
                    mma_bf16(acc[mt][nt], am[mt], bl);
                }
            }
        }
        __syncthreads();
    }

#pragma unroll
    for (int mt = 0; mt < 2; mt++) {
#pragma unroll
        for (int nt = 0; nt < 4; nt++) {
            int row0 = bm + wm + mt * 16 + grp;
            int col = bn + wn + nt * 8 + tig * 2;
            float2 bv = *(const float2*)(bias + col);
            float d0 = dis[row0];
            float d1 = dis[row0 + 8];
            float2 o0 = make_float2(d0 * acc[mt][nt][0] + bv.x,
                                    d0 * acc[mt][nt][1] + bv.y);
            float2 o1 = make_float2(d1 * acc[mt][nt][2] + bv.x,
                                    d1 * acc[mt][nt][3] + bv.y);
            *(float2*)(out + (size_t)row0 * GCN_ + col) = o0;
            *(float2*)(out + (size_t)(row0 + 8) * GCN_ + col) = o1;
        }
    }
}

// ---------------------------------------------------------------------------
// Sorting: rows by slen; nnz by edge and by node (fused setup kernels)
// ---------------------------------------------------------------------------
__global__ void setup_zero_kernel(int* __restrict__ hist, int* __restrict__ cur,
                                  int* __restrict__ ecnt, int* __restrict__ ecur,
                                  int* __restrict__ ncnt, int* __restrict__ ncur,
                                  float* __restrict__ deg)
{
    int i = blockIdx.x * 256 + threadIdx.x;
    if (i < 32) { hist[i] = 0; cur[i] = 0; }
    if (i < E_) { ecnt[i] = 0; ecur[i] = 0; }
    if (i < NN_) { ncnt[i] = 0; ncur[i] = 0; deg[i] = 0.f; }
}

__global__ void hist_kernel(const int* __restrict__ slen, int* __restrict__ hist)
{
    int i = blockIdx.x * 256 + threadIdx.x;
    if (i < NN_) atomicAdd(&hist[slen[i] - 1], 1);
}

__global__ void scan_kernel(const int* __restrict__ hist,
                            int* __restrict__ cnt, int* __restrict__ start)
{
    if (threadIdx.x == 0) {
        int run = 0;
        cnt[T_] = 0;
        for (int s = T_ - 1; s >= 0; s--) {
            start[s] = run;
            run += hist[s];
            cnt[s] = run;
        }
    }
}

__global__ void scatter_perm_kernel(const int* __restrict__ slen,
                                    const int* __restrict__ start,
                                    int* __restrict__ cur,
                                    int* __restrict__ perm)
{
    int i = blockIdx.x * 256 + threadIdx.x;
    if (i < NN_) {
        int s = slen[i] - 1;
        int pos = start[s] + atomicAdd(&cur[s], 1);
        perm[pos] = i;
    }
}

__global__ void hist_nz_kernel(const int* __restrict__ node_idx,
                               const int* __restrict__ edge_idx,
                               int* __restrict__ ncnt, int* __restrict__ ecnt)
{
    int i = blockIdx.x * 256 + threadIdx.x;
    if (i < NNZ_) {
        atomicAdd(&ncnt[node_idx[i]], 1);
        atomicAdd(&ecnt[edge_idx[i]], 1);
    }
}

__global__ void scan_bins_kernel(const int* __restrict__ cnt,
                                 int* __restrict__ off, int n)
{
    __shared__ int part[1024];
    int tid = threadIdx.x;
    int per = n / 1024;
    int base = tid * per;
    int s = 0;
    for (int i = 0; i < per; i++) s += cnt[base + i];
    part[tid] = s;
    __syncthreads();
    for (int d = 1; d < 1024; d <<= 1) {
        int v = (tid >= d) ? part[tid - d] : 0;
        __syncthreads();
        part[tid] += v;
        __syncthreads();
    }
    int run = part[tid] - s;
    for (int i = 0; i < per; i++) {
        off[base + i] = run;
        run += cnt[base + i];
    }
    if (tid == 1023) off[n] = run;
}

__global__ void scatter_orders_kernel(const int* __restrict__ node_idx,
                                      const int* __restrict__ edge_idx,
                                      const int* __restrict__ eoff,
                                      const int* __restrict__ noff,
                                      int* __restrict__ ecur,
                                      int* __restrict__ ncur,
                                      int* __restrict__ eorder,
                                      int* __restrict__ norder)
{
    int i = blockIdx.x * 256 + threadIdx.x;
    if (i < NNZ_) {
        int e = edge_idx[i];
        int pe = eoff[e] + atomicAdd(&ecur[e], 1);
        eorder[pe] = i;
        int n = node_idx[i];
        int pn = noff[n] + atomicAdd(&ncur[n], 1);
        norder[pn] = i;
    }
}

__global__ void inv_both_kernel(const int* __restrict__ ecnt,
                                const int* __restrict__ ncnt,
                                float* __restrict__ Binv,
                                float* __restrict__ Dinv)
{
    int i = blockIdx.x * 256 + threadIdx.x;
    if (i < E_) {
        int c = ecnt[i];
        Binv[i] = c > 0 ? 1.f / (float)c : 0.f;
    }
    if (i < NN_) {
        int c = ncnt[i];
        Dinv[i] = c > 0 ? 1.f / (float)c : 0.f;
    }
}

__global__ void init_h_kernel(float* __restrict__ h, const float* __restrict__ h0)
{
    int idx = blockIdx.x * 256 + threadIdx.x;
    h[idx] = h0[idx & (H_ - 1)];
}

// ---------------------------------------------------------------------------
// HGC segment sums (atomic-free)
// ---------------------------------------------------------------------------
__global__ void edge_sum_kernel(const float* __restrict__ xw,
                                const int* __restrict__ node_idx,
                                const int* __restrict__ eorder,
                                const int* __restrict__ eoff,
                                const float* __restrict__ Binv,
                                float* __restrict__ eb)
{
    int e = blockIdx.x;
    int c = threadIdx.x;
    int s0 = eoff[e], s1 = eoff[e + 1];
    float s = 0.f;
    for (int j = s0; j < s1; j++) {
        int nz = eorder[j];
        s += xw[(size_t)node_idx[nz] * H_ + c];
    }
    eb[(size_t)e * H_ + c] = s * Binv[e];
}

__global__ void node_sum_kernel(const float* __restrict__ eb,
                                const int* __restrict__ edge_idx,
                                const int* __restrict__ norder,
                                const int* __restrict__ noff,
                                const float* __restrict__ Dinv,
                                const float* __restrict__ bias,
                                const float* __restrict__ resid,
                                float* __restrict__ out)
{
    int n = blockIdx.x * 8 + (threadIdx.x >> 5);
    int lane = threadIdx.x & 31;
    int s0 = noff[n], s1 = noff[n + 1];
    float s[8];
#pragma unroll
    for (int k = 0; k < 8; k++) s[k] = 0.f;
    for (int j = s0; j < s1; j++) {
        int e = edge_idx[norder[j]];
        const float* er = eb + (size_t)e * H_;
#pragma unroll
        for (int k = 0; k < 8; k++) s[k] += er[lane + k * 32];
    }
    float di = Dinv[n];
#pragma unroll
    for (int k = 0; k < 8; k++) {
        int c = lane + k * 32;
        out[(size_t)n * H_ + c] = s[k] * di + bias[c] + resid[(size_t)n * H_ + c];
    }
}

__global__ void dis_kernel(const float* __restrict__ deg, float* __restrict__ dis)
{
    int i = blockIdx.x * 256 + threadIdx.x;
    if (i < NN_) {
        float d = deg[i];
        dis[i] = d > 0.f ? rsqrtf(d) : 0.f;
    }
}

// ---------------------------------------------------------------------------
// Host orchestration
// ---------------------------------------------------------------------------
extern "C" void kernel_launch(void* const* d_in, const int* in_sizes, int n_in,
                              void* d_out, int out_size)
{
    (void)in_sizes; (void)n_in; (void)out_size;

    const float* x        = (const float*)d_in[0];
    const int*   hei      = (const int*)d_in[1];
    const int*   node_idx = hei;
    const int*   edge_idx = hei + NNZ_;
    const int*   slen     = (const int*)d_in[2];
    const float* h0       = (const float*)d_in[3];
    const float* W_ih     = (const float*)d_in[4];
    const float* W_hh     = (const float*)d_in[5];
    const float* b_ih     = (const float*)d_in[6];
    const float* b_hh     = (const float*)d_in[7];
    const float* w1 = (const float*)d_in[8];  const float* bb1 = (const float*)d_in[9];
    const float* w2 = (const float*)d_in[10]; const float* bb2 = (const float*)d_in[11];
    const float* w3 = (const float*)d_in[12]; const float* bb3 = (const float*)d_in[13];
    const float* phi = (const float*)d_in[14];
    const float* gw  = (const float*)d_in[15];
    const float* gb  = (const float*)d_in[16];
    float* out = (float*)d_out;

    float *xgall, *h, *h2, *fa, *fb, *xw, *eb, *x2, *deg, *Dinv, *Binv, *dis;
    unsigned char* mask;
    __nv_bfloat16 *whh_h, *whh_l, *wih_h, *wih_l, *o3h, *o3l, *yth, *ytl, *wt_h, *wt_l;
    int *perm, *histb, *curb, *startb, *cntb;
    int *ecnt, *ncnt, *ecur, *ncur, *eoff, *noff, *eorder, *norder;
    cudaGetSymbolAddress((void**)&xgall, g_xgall);
    cudaGetSymbolAddress((void**)&h,     g_h);
    cudaGetSymbolAddress((void**)&h2,    g_h2);
    cudaGetSymbolAddress((void**)&fa,    g_fa);
    cudaGetSymbolAddress((void**)&fb,    g_fb);
    cudaGetSymbolAddress((void**)&xw,    g_xw);
    cudaGetSymbolAddress((void**)&eb,    g_eb);
    cudaGetSymbolAddress((void**)&x2,    g_x2);
    cudaGetSymbolAddress((void**)&mask,  g_mask);
    cudaGetSymbolAddress((void**)&deg,   g_deg);
    cudaGetSymbolAddress((void**)&Dinv,  g_Dinv);
    cudaGetSymbolAddress((void**)&Binv,  g_Binv);
    cudaGetSymbolAddress((void**)&dis,   g_dis);
    cudaGetSymbolAddress((void**)&whh_h, g_whh_h);
    cudaGetSymbolAddress((void**)&whh_l, g_whh_l);
    cudaGetSymbolAddress((void**)&wih_h, g_wih_h);
    cudaGetSymbolAddress((void**)&wih_l, g_wih_l);
    cudaGetSymbolAddress((void**)&o3h,   g_o3h);
    cudaGetSymbolAddress((void**)&o3l,   g_o3l);
    cudaGetSymbolAddress((void**)&yth,   g_yth);
    cudaGetSymbolAddress((void**)&ytl,   g_ytl);
    cudaGetSymbolAddress((void**)&wt_h,  g_wt_h);
    cudaGetSymbolAddress((void**)&wt_l,  g_wt_l);
    cudaGetSymbolAddress((void**)&perm,  g_perm);
    cudaGetSymbolAddress((void**)&histb, g_hist);
    cudaGetSymbolAddress((void**)&curb,  g_cur);
    cudaGetSymbolAddress((void**)&startb,g_start);
    cudaGetSymbolAddress((void**)&cntb,  g_cnt);
    cudaGetSymbolAddress((void**)&ecnt,  g_ecnt);
    cudaGetSymbolAddress((void**)&ncnt,  g_ncnt);
    cudaGetSymbolAddress((void**)&ecur,  g_ecur);
    cudaGetSymbolAddress((void**)&ncur,  g_ncur);
    cudaGetSymbolAddress((void**)&eoff,  g_eoff);
    cudaGetSymbolAddress((void**)&noff,  g_noff);
    cudaGetSymbolAddress((void**)&eorder,g_eorder);
    cudaGetSymbolAddress((void**)&norder,g_norder);

    const int XG_SMEM  = 4 * 128 * XS_ * 2;                        // 90112 B
    const int GRU_SMEM = (2 * 64 * GS_ + 4 * GBB_) * 2;            // 129024 B
    cudaFuncSetAttribute(xg_gemm_mma,
                         cudaFuncAttributeMaxDynamicSharedMemorySize, XG_SMEM);
    cudaFuncSetAttribute(gru_step_mma,
                         cudaFuncAttributeMaxDynamicSharedMemorySize, GRU_SMEM);
    cudaFuncSetAttribute(sgemm_nt_mma,
                         cudaFuncAttributeMaxDynamicSharedMemorySize, XG_SMEM);
    cudaFuncSetAttribute(gram_mma,
                         cudaFuncAttributeMaxDynamicSharedMemorySize, XG_SMEM);

    // ---------------- fused setup ----------------
    setup_zero_kernel<<<NN_ / 256, 256>>>(histb, curb, ecnt, ecur, ncnt, ncur, deg);
    hist_kernel<<<NN_ / 256, 256>>>(slen, histb);
    scan_kernel<<<1, 32>>>(histb, cntb, startb);
    scatter_perm_kernel<<<NN_ / 256, 256>>>(slen, startb, curb, perm);

    hist_nz_kernel<<<NNZ_ / 256, 256>>>(node_idx, edge_idx, ncnt, ecnt);
    scan_bins_kernel<<<1, 1024>>>(ecnt, eoff, E_);
    scan_bins_kernel<<<1, 1024>>>(ncnt, noff, NN_);
    scatter_orders_kernel<<<NNZ_ / 256, 256>>>(node_idx, edge_idx, eoff, noff,
                                               ecur, ncur, eorder, norder);
    inv_both_kernel<<<NN_ / 256, 256>>>(ecnt, ncnt, Binv, Dinv);

    // ---------------- one-time weight splits ----------------
    split_w_kernel<<<(H3_ * H_ + 255) / 256, 256>>>(W_hh, whh_h, whh_l, H3_ * H_);
    split_w_kernel<<<(H3_ * IN_ + 255) / 256, 256>>>(W_ih, wih_h, wih_l, H3_ * IN_);
    wt_split_kernel<<<dim3(8, 8), dim3(32, 8)>>>(w1, wt_h, wt_l);
    wt_split_kernel<<<dim3(8, 8), dim3(32, 8)>>>(w2, wt_h + H_ * H_, wt_l + H_ * H_);
    wt_split_kernel<<<dim3(8, 8), dim3(32, 8)>>>(w3, wt_h + 2 * H_ * H_, wt_l + 2 * H_ * H_);
    wt_split_kernel<<<dim3(8, 8), dim3(32, 8)>>>(gw, wt_h + 3 * H_ * H_, wt_l + 3 * H_ * H_);

    // ---------------- GRU ----------------
    init_h_kernel<<<NN_ * H_ / 256, 256>>>(h, h0);
    xg_gemm_mma<<<dim3(H3_ / 128, T_ * NN_ / 128), 256, XG_SMEM>>>(
        x, wih_h, wih_l, b_ih, perm, cntb, xgall);

    float* hrd = h;
    float* hwr = h2;
    for (int t = 0; t < T_; t++) {
        gru_step_mma<<<dim3(H_ / 64, NN_ / 64), 256, GRU_SMEM>>>(
            whh_h, whh_l, b_hh, xgall, hrd, hwr, perm, cntb, fa, t);
        float* tmp = hrd; hrd = hwr; hwr = tmp;
    }
    // fa holds `last` in original row order

    // ---------------- 3 hypergraph conv layers (atomic-free) ----------------
    const float* hgc_in[3]  = {fa, fb, fa};
    float*       hgc_out[3] = {fb, fa, fb};
    const float* hgc_b[3]   = {bb1, bb2, bb3};
    for (int l = 0; l < 3; l++) {
        sgemm_nt_mma<<<dim3(2, NN_ / 128), 256, XG_SMEM>>>(
            hgc_in[l], wt_h + l * H_ * H_, wt_l + l * H_ * H_, xw);
        edge_sum_kernel<<<E_, 256>>>(xw, node_idx, eorder, eoff, Binv, eb);
        node_sum_kernel<<<NN_ / 8, 256>>>(eb, edge_idx, norder, noff, Dinv,
                                          hgc_b[l], hgc_in[l], hgc_out[l]);
    }
    // fb holds o3

    // ---------------- final dense GCN ----------------
    sgemm_nt_mma<<<dim3(2, NN_ / 128), 256, XG_SMEM>>>(
        fb, wt_h + 3 * H_ * H_, wt_l + 3 * H_ * H_, x2);

    split_w_kernel<<<(NN_ * H_ + 255) / 256, 256>>>(fb, o3h, o3l, NN_ * H_);
    gram_mma<<<64 * 65 / 2, 256, XG_SMEM>>>(o3h, o3l, mask, deg, phi);
    dis_kernel<<<(NN_ + 255) / 256, 256>>>(deg, dis);
    yt_split_kernel<<<dim3(NN_ / 32, GCN_ / 32), dim3(32, 8)>>>(x2, dis, yth, ytl);
    gcn_gemm_mma<<<dim3(GCN_ / 64, NN_ / 128), 256>>>(mask, yth, ytl, dis, gb, out);
}

// round 15
// speedup vs baseline: 1.1148x; 1.1148x over previous
#include <cuda_runtime.h>
#include <cuda_bf16.h>
#include <cstdint>
#include <cstdio>

// Problem constants
#define NN_   8192
#define T_    32
#define IN_   256
#define H_    256
#define H3_   768
#define E_    1024
#define NNZ_  65536
#define GCN_  256

// ---------------------------------------------------------------------------
// Scratch (static device globals; no runtime allocation)
// ---------------------------------------------------------------------------
__device__ float g_xgall[(size_t)NN_ * T_ * H3_];   // [t][pos][768] t-major, sorted rows
__device__ float g_h [NN_ * H_];
__device__ float g_h2[NN_ * H_];
__device__ float g_fa[NN_ * H_];                    // feature ping (last / o2)
__device__ float g_fb[NN_ * H_];                    // feature pong (o1 / o3)
__device__ float g_xw[NN_ * H_];                    // HGC x@W
__device__ float g_eb[E_ * H_];                     // HGC edge accumulator
__device__ float g_x2[NN_ * GCN_];                  // o3 @ gcn_w
__device__ unsigned char g_mask[(size_t)NN_ * NN_]; // 64 MB adjacency mask bytes
__device__ float g_deg[NN_];
__device__ float g_Dinv[NN_];
__device__ float g_Binv[E_];
__device__ float g_dis[NN_];
// bf16 pre-split buffers
__device__ __nv_bfloat16 g_whh_h[H3_ * H_];
__device__ __nv_bfloat16 g_whh_l[H3_ * H_];
__device__ __nv_bfloat16 g_wih_h[H3_ * IN_];
__device__ __nv_bfloat16 g_wih_l[H3_ * IN_];
__device__ __nv_bfloat16 g_o3h[NN_ * H_];
__device__ __nv_bfloat16 g_o3l[NN_ * H_];
__device__ __nv_bfloat16 g_yth[(size_t)GCN_ * NN_];
__device__ __nv_bfloat16 g_ytl[(size_t)GCN_ * NN_];
__device__ __nv_bfloat16 g_wt_h[4 * H_ * H_];       // w1,w2,w3,gcn_w transposed+split
__device__ __nv_bfloat16 g_wt_l[4 * H_ * H_];
// sequence-length sort
__device__ int g_perm[NN_];
__device__ int g_hist[32];
__device__ int g_cur[32];
__device__ int g_start[32];
__device__ int g_cnt[T_ + 1];
// nnz segment sort (by edge, by node)
__device__ int g_ecnt[E_];
__device__ int g_ncnt[NN_];
__device__ int g_ecur[E_];
__device__ int g_ncur[NN_];
__device__ int g_eoff[E_ + 1];
__device__ int g_noff[NN_ + 1];
__device__ int g_eorder[NNZ_];
__device__ int g_norder[NNZ_];

// ---------------------------------------------------------------------------
// helpers
// ---------------------------------------------------------------------------
__device__ __forceinline__ float sigf(float x)
{
    return 1.f / (1.f + __expf(-x));
}

__device__ __forceinline__ void split8(const float* __restrict__ s, uint4& hi, uint4& lo)
{
    float4 v0 = *(const float4*)s;
    float4 v1 = *(const float4*)(s + 4);
    float vv[8] = {v0.x, v0.y, v0.z, v0.w, v1.x, v1.y, v1.z, v1.w};
    unsigned hw[4], lw[4];
#pragma unroll
    for (int p = 0; p < 4; p++) {
        __nv_bfloat16 h0 = __float2bfloat16(vv[2 * p]);
        __nv_bfloat16 h1 = __float2bfloat16(vv[2 * p + 1]);
        __nv_bfloat16 l0 = __float2bfloat16(vv[2 * p] - __bfloat162float(h0));
        __nv_bfloat16 l1 = __float2bfloat16(vv[2 * p + 1] - __bfloat162float(h1));
        __nv_bfloat162 hp = __halves2bfloat162(h0, h1);
        __nv_bfloat162 lp = __halves2bfloat162(l0, l1);
        hw[p] = *(unsigned*)&hp;
        lw[p] = *(unsigned*)&lp;
    }
    hi = make_uint4(hw[0], hw[1], hw[2], hw[3]);
    lo = make_uint4(lw[0], lw[1], lw[2], lw[3]);
}

__device__ __forceinline__ void mma_bf16(float* c, const uint32_t* a, const uint32_t* b)
{
    asm volatile(
        "mma.sync.aligned.m16n8k16.row.col.f32.bf16.bf16.f32 "
        "{%0,%1,%2,%3}, {%4,%5,%6,%7}, {%8,%9}, {%0,%1,%2,%3};"
        : "+f"(c[0]), "+f"(c[1]), "+f"(c[2]), "+f"(c[3])
        : "r"(a[0]), "r"(a[1]), "r"(a[2]), "r"(a[3]), "r"(b[0]), "r"(b[1]));
}

// ---------------------------------------------------------------------------
// One-time split kernels
// ---------------------------------------------------------------------------
__global__ void split_w_kernel(const float* __restrict__ W,
                               __nv_bfloat16* __restrict__ Wh,
                               __nv_bfloat16* __restrict__ Wl, int n)
{
    int i = blockIdx.x * 256 + threadIdx.x;
    if (i < n) {
        float v = W[i];
        __nv_bfloat16 h = __float2bfloat16(v);
        Wh[i] = h;
        Wl[i] = __float2bfloat16(v - __bfloat162float(h));
    }
}

// Transpose + split a [K=256][N=256] weight -> [n][k] bf16 hi/lo.
__global__ void wt_split_kernel(const float* __restrict__ W,
                                __nv_bfloat16* __restrict__ Wth,
                                __nv_bfloat16* __restrict__ Wtl)
{
    __shared__ float tile[32][33];
    int kb = blockIdx.x * 32;
    int nb = blockIdx.y * 32;
    int tx = threadIdx.x, ty = threadIdx.y;
    for (int i = ty; i < 32; i += 8)
        tile[i][tx] = W[(size_t)(kb + i) * H_ + nb + tx];
    __syncthreads();
    for (int i = ty; i < 32; i += 8) {
        float v = tile[tx][i];
        __nv_bfloat16 h = __float2bfloat16(v);
        Wth[(size_t)(nb + i) * H_ + kb + tx] = h;
        Wtl[(size_t)(nb + i) * H_ + kb + tx] = __float2bfloat16(v - __bfloat162float(h));
    }
}

// Y^T build: Yt[n][k] = dis[k] * x2[k][n], split hi/lo bf16.
__global__ void yt_split_kernel(const float* __restrict__ x2,
                                const float* __restrict__ dis,
                                __nv_bfloat16* __restrict__ Yth,
                                __nv_bfloat16* __restrict__ Ytl)
{
    __shared__ float tile[32][33];
    int kb = blockIdx.x * 32;
    int nb = blockIdx.y * 32;
    int tx = threadIdx.x, ty = threadIdx.y;
    for (int i = ty; i < 32; i += 8)
        tile[i][tx] = x2[(size_t)(kb + i) * GCN_ + nb + tx] * dis[kb + i];
    __syncthreads();
    for (int i = ty; i < 32; i += 8) {
        float v = tile[tx][i];
        __nv_bfloat16 h = __float2bfloat16(v);
        Yth[(size_t)(nb + i) * NN_ + kb + tx] = h;
        Ytl[(size_t)(nb + i) * NN_ + kb + tx] = __float2bfloat16(v - __bfloat162float(h));
    }
}

// ---------------------------------------------------------------------------
// Tensor-core input-gate GEMM (round-10 proven).
// ---------------------------------------------------------------------------
#define XS_ 88
__global__ __launch_bounds__(256, 2)
void xg_gemm_mma(const float* __restrict__ x,
                 const __nv_bfloat16* __restrict__ Wih_h,
                 const __nv_bfloat16* __restrict__ Wih_l,
                 const float* __restrict__ bih,
                 const int* __restrict__ perm,
                 const int* __restrict__ cnt,
                 float* __restrict__ xgall)
{
    const int bm = blockIdx.y * 128;
    const int t = bm >> 13;
    const int pos0 = bm & (NN_ - 1);
    if (pos0 >= cnt[t]) return;
    const int bn = blockIdx.x * 128;

    extern __shared__ __align__(16) __nv_bfloat16 smx[];
    __nv_bfloat16* Ah = smx;
    __nv_bfloat16* Al = smx + 128 * XS_;
    __nv_bfloat16* Bh = smx + 2 * 128 * XS_;
    __nv_bfloat16* Bl = smx + 3 * 128 * XS_;

    const int tid = threadIdx.x;
    const int wid = tid >> 5;
    const int lane = tid & 31;
    const int wm = (wid & 3) * 32;
    const int wn = (wid >> 2) * 64;
    const int grp = lane >> 2;
    const int tig = lane & 3;

    float acc[2][8][4];
#pragma unroll
    for (int mt = 0; mt < 2; mt++)
#pragma unroll
        for (int nt = 0; nt < 8; nt++)
#pragma unroll
            for (int e = 0; e < 4; e++) acc[mt][nt][e] = 0.f;

    for (int kc = 0; kc < 4; kc++) {
#pragma unroll
        for (int i = 0; i < 4; i++) {
            int u = i * 256 + tid;
            int r = u >> 3;
            int cg = u & 7;
            uint4 hi, lo;
            split8(x + (size_t)perm[pos0 + r] * (T_ * IN_) + t * IN_ + kc * 64 + cg * 8,
                   hi, lo);
            *(uint4*)(Ah + r * XS_ + cg * 8) = hi;
            *(uint4*)(Al + r * XS_ + cg * 8) = lo;
        }
#pragma unroll
        for (int i = 0; i < 4; i++) {
            int u = i * 256 + tid;
            int r = u >> 3;
            int cg = u & 7;
            size_t goff = (size_t)(bn + r) * IN_ + kc * 64 + cg * 8;
            *(uint4*)(Bh + r * XS_ + cg * 8) = *(const uint4*)(Wih_h + goff);
            *(uint4*)(Bl + r * XS_ + cg * 8) = *(const uint4*)(Wih_l + goff);
        }
        __syncthreads();

#pragma unroll
        for (int ks = 0; ks < 4; ks++) {
            const int kk = ks * 16;
            uint32_t ah[2][4], al[2][4];
#pragma unroll
            for (int mt = 0; mt < 2; mt++) {
                int r0 = wm + mt * 16 + grp;
                ah[mt][0] = *(const uint32_t*)(Ah + (size_t)r0 * XS_ + kk + tig * 2);
                ah[mt][1] = *(const uint32_t*)(Ah + (size_t)(r0 + 8) * XS_ + kk + tig * 2);
                ah[mt][2] = *(const uint32_t*)(Ah + (size_t)r0 * XS_ + kk + 8 + tig * 2);
                ah[mt][3] = *(const uint32_t*)(Ah + (size_t)(r0 + 8) * XS_ + kk + 8 + tig * 2);
                al[mt][0] = *(const uint32_t*)(Al + (size_t)r0 * XS_ + kk + tig * 2);
                al[mt][1] = *(const uint32_t*)(Al + (size_t)(r0 + 8) * XS_ + kk + tig * 2);
                al[mt][2] = *(const uint32_t*)(Al + (size_t)r0 * XS_ + kk + 8 + tig * 2);
                al[mt][3] = *(const uint32_t*)(Al + (size_t)(r0 + 8) * XS_ + kk + 8 + tig * 2);
            }
#pragma unroll
            for (int nt = 0; nt < 8; nt++) {
                int nr = wn + nt * 8 + grp;
                uint32_t bh[2], bl[2];
                bh[0] = *(const uint32_t*)(Bh + (size_t)nr * XS_ + kk + tig * 2);
                bh[1] = *(const uint32_t*)(Bh + (size_t)nr * XS_ + kk + 8 + tig * 2);
                bl[0] = *(const uint32_t*)(Bl + (size_t)nr * XS_ + kk + tig * 2);
                bl[1] = *(const uint32_t*)(Bl + (size_t)nr * XS_ + kk + 8 + tig * 2);
#pragma unroll
                for (int mt = 0; mt < 2; mt++) {
                    mma_bf16(acc[mt][nt], ah[mt], bh);
                    mma_bf16(acc[mt][nt], ah[mt], bl);
                    mma_bf16(acc[mt][nt], al[mt], bh);
                }
            }
        }
        __syncthreads();
    }

#pragma unroll
    for (int mt = 0; mt < 2; mt++) {
#pragma unroll
        for (int nt = 0; nt < 8; nt++) {
            int row0 = bm + wm + mt * 16 + grp;
            int col = bn + wn + nt * 8 + tig * 2;
            float2 bv = *(const float2*)(bih + col);
            float2 o0 = make_float2(acc[mt][nt][0] + bv.x, acc[mt][nt][1] + bv.y);
            float2 o1 = make_float2(acc[mt][nt][2] + bv.x, acc[mt][nt][3] + bv.y);
            *(float2*)(xgall + (size_t)row0 * H3_ + col) = o0;
            *(float2*)(xgall + (size_t)(row0 + 8) * H3_ + col) = o1;
        }
    }
}

// ---------------------------------------------------------------------------
// Fused GRU step (round-13 champion; synchronous loads, no reg cap).
// ---------------------------------------------------------------------------
#define GS_ 72
__global__ __launch_bounds__(256)
void gru_step_mma(const __nv_bfloat16* __restrict__ Whh_h,
                  const __nv_bfloat16* __restrict__ Whh_l,
                  const float* __restrict__ bhh,
                  const float* __restrict__ xgall,
                  const float* __restrict__ hin,
                  float* __restrict__ hout,
                  const int* __restrict__ perm,
                  const int* __restrict__ cnt,
                  float* __restrict__ last, int t)
{
    const int bm = blockIdx.y * 64;
    const int c0 = cnt[t];
    if (bm >= c0) return;
    const int c1 = cnt[t + 1];
    const int bn = blockIdx.x * 64;

    extern __shared__ __align__(16) __nv_bfloat16 smg[];
    __nv_bfloat16* Ah = smg;
    __nv_bfloat16* Al = smg + 64 * GS_;
    __nv_bfloat16* Bh = smg + 2 * 64 * GS_;
    __nv_bfloat16* Bl = smg + 2 * 64 * GS_ + 192 * GS_;

    const int tid = threadIdx.x;
    const int wid = tid >> 5;
    const int lane = tid & 31;
    const int wm = (wid & 1) * 32;
    const int wn16 = (wid >> 1) * 16;
    const int grp = lane >> 2;
    const int tig = lane & 3;

    float acc[2][3][2][4];
#pragma unroll
    for (int mt = 0; mt < 2; mt++)
#pragma unroll
        for (int g = 0; g < 3; g++)
#pragma unroll
            for (int nt = 0; nt < 2; nt++)
#pragma unroll
                for (int e = 0; e < 4; e++) acc[mt][g][nt][e] = 0.f;

    for (int kc = 0; kc < 4; kc++) {
#pragma unroll
        for (int i = 0; i < 2; i++) {
            int u = i * 256 + tid;
            int r = u >> 3;
            int cg = u & 7;
            uint4 hi, lo;
            split8(hin + (size_t)(bm + r) * H_ + kc * 64 + cg * 8, hi, lo);
            *(uint4*)(Ah + r * GS_ + cg * 8) = hi;
            *(uint4*)(Al + r * GS_ + cg * 8) = lo;
        }
#pragma unroll
        for (int i = 0; i < 6; i++) {
            int u = i * 256 + tid;
            int r = u >> 3;
            int cg = u & 7;
            int g = r >> 6;
            int br = r & 63;
            size_t goff = (size_t)(g * 256 + bn + br) * H_ + kc * 64 + cg * 8;
            *(uint4*)(Bh + r * GS_ + cg * 8) = *(const uint4*)(Whh_h + goff);
            *(uint4*)(Bl + r * GS_ + cg * 8) = *(const uint4*)(Whh_l + goff);
        }
        __syncthreads();

#pragma unroll
        for (int ks = 0; ks < 4; ks++) {
            const int kk = ks * 16;
            uint32_t ah[2][4], al[2][4];
#pragma unroll
            for (int mt = 0; mt < 2; mt++) {
                int r0 = wm + mt * 16 + grp;
                ah[mt][0] = *(const uint32_t*)(Ah + (size_t)r0 * GS_ + kk + tig * 2);
                ah[mt][1] = *(const uint32_t*)(Ah + (size_t)(r0 + 8) * GS_ + kk + tig * 2);
                ah[mt][2] = *(const uint32_t*)(Ah + (size_t)r0 * GS_ + kk + 8 + tig * 2);
                ah[mt][3] = *(const uint32_t*)(Ah + (size_t)(r0 + 8) * GS_ + kk + 8 + tig * 2);
                al[mt][0] = *(const uint32_t*)(Al + (size_t)r0 * GS_ + kk + tig * 2);
                al[mt][1] = *(const uint32_t*)(Al + (size_t)(r0 + 8) * GS_ + kk + tig * 2);
                al[mt][2] = *(const uint32_t*)(Al + (size_t)r0 * GS_ + kk + 8 + tig * 2);
                al[mt][3] = *(const uint32_t*)(Al + (size_t)(r0 + 8) * GS_ + kk + 8 + tig * 2);
            }
#pragma unroll
            for (int g = 0; g < 3; g++) {
#pragma unroll
                for (int nt = 0; nt < 2; nt++) {
                    int nr = g * 64 + wn16 + nt * 8 + grp;
                    uint32_t bh[2], bl[2];
                    bh[0] = *(const uint32_t*)(Bh + (size_t)nr * GS_ + kk + tig * 2);
                    bh[1] = *(const uint32_t*)(Bh + (size_t)nr * GS_ + kk + 8 + tig * 2);
                    bl[0] = *(const uint32_t*)(Bl + (size_t)nr * GS_ + kk + tig * 2);
                    bl[1] = *(const uint32_t*)(Bl + (size_t)nr * GS_ + kk + 8 + tig * 2);
#pragma unroll
                    for (int mt = 0; mt < 2; mt++) {
                        mma_bf16(acc[mt][g][nt], ah[mt], bh);
                        mma_bf16(acc[mt][g][nt], ah[mt], bl);
                        mma_bf16(acc[mt][g][nt], al[mt], bh);
                    }
                }
            }
        }
        __syncthreads();
    }

#pragma unroll
    for (int mt = 0; mt < 2; mt++) {
        int rbase = bm + wm + mt * 16 + grp;
#pragma unroll
        for (int half = 0; half < 2; half++) {
            int row = rbase + half * 8;
            bool isLast = (row >= c1 && row < c0);
            int pr = isLast ? perm[row] : 0;
            size_t xb = ((size_t)t * NN_ + row) * H3_;
            size_t hb = (size_t)row * H_;
#pragma unroll
            for (int nt = 0; nt < 2; nt++) {
                int col = bn + wn16 + nt * 8 + tig * 2;
                float2 xr = *(const float2*)(xgall + xb + col);
                float2 xz = *(const float2*)(xgall + xb + 256 + col);
                float2 xq = *(const float2*)(xgall + xb + 512 + col);
                float2 ho = *(const float2*)(hin + hb + col);
                float2 br = *(const float2*)(bhh + col);
                float2 bz = *(const float2*)(bhh + 256 + col);
                float2 bq = *(const float2*)(bhh + 512 + col);
                float hr0 = acc[mt][0][nt][half * 2 + 0];
                float hr1 = acc[mt][0][nt][half * 2 + 1];
                float hz0 = acc[mt][1][nt][half * 2 + 0];
                float hz1 = acc[mt][1][nt][half * 2 + 1];
                float hq0 = acc[mt][2][nt][half * 2 + 0];
                float hq1 = acc[mt][2][nt][half * 2 + 1];
                float r0 = sigf(xr.x + hr0 + br.x);
                float z0 = sigf(xz.x + hz0 + bz.x);
                float q0 = tanhf(xq.x + r0 * (hq0 + bq.x));
                float r1 = sigf(xr.y + hr1 + br.y);
                float z1 = sigf(xz.y + hz1 + bz.y);
                float q1 = tanhf(xq.y + r1 * (hq1 + bq.y));
                float2 hn = make_float2((1.f - z0) * q0 + z0 * ho.x,
                                        (1.f - z1) * q1 + z1 * ho.y);
                *(float2*)(hout + hb + col) = hn;
                if (isLast)
                    *(float2*)(last + (size_t)pr * H_ + col) = hn;
            }
        }
    }
}

// ---------------------------------------------------------------------------
// HMMA NT GEMM (round-8 proven): C[M,256] = A (fp32 split) @ Wt (pre-split).
// ---------------------------------------------------------------------------
__global__ __launch_bounds__(256, 2)
void sgemm_nt_mma(const float* __restrict__ A,
                  const __nv_bfloat16* __restrict__ Wth,
                  const __nv_bfloat16* __restrict__ Wtl,
                  float* __restrict__ C)
{
    const int bm = blockIdx.y * 128;
    const int bn = blockIdx.x * 128;

    extern __shared__ __align__(16) __nv_bfloat16 smn[];
    __nv_bfloat16* Ah = smn;
    __nv_bfloat16* Al = smn + 128 * XS_;
    __nv_bfloat16* Bh = smn + 2 * 128 * XS_;
    __nv_bfloat16* Bl = smn + 3 * 128 * XS_;

    const int tid = threadIdx.x;
    const int wid = tid >> 5;
    const int lane = tid & 31;
    const int wm = (wid & 3) * 32;
    const int wn = (wid >> 2) * 64;
    const int grp = lane >> 2;
    const int tig = lane & 3;

    float acc[2][8][4];
#pragma unroll
    for (int mt = 0; mt < 2; mt++)
#pragma unroll
        for (int nt = 0; nt < 8; nt++)
#pragma unroll
            for (int e = 0; e < 4; e++) acc[mt][nt][e] = 0.f;

    for (int kc = 0; kc < 4; kc++) {
#pragma unroll
        for (int i = 0; i < 4; i++) {
            int u = i * 256 + tid;
            int r = u >> 3;
            int cg = u & 7;
            uint4 hi, lo;
            split8(A + (size_t)(bm + r) * H_ + kc * 64 + cg * 8, hi, lo);
            *(uint4*)(Ah + r * XS_ + cg * 8) = hi;
            *(uint4*)(Al + r * XS_ + cg * 8) = lo;
        }
#pragma unroll
        for (int i = 0; i < 4; i++) {
            int u = i * 256 + tid;
            int r = u >> 3;
            int cg = u & 7;
            size_t goff = (size_t)(bn + r) * H_ + kc * 64 + cg * 8;
            *(uint4*)(Bh + r * XS_ + cg * 8) = *(const uint4*)(Wth + goff);
            *(uint4*)(Bl + r * XS_ + cg * 8) = *(const uint4*)(Wtl + goff);
        }
        __syncthreads();

#pragma unroll
        for (int ks = 0; ks < 4; ks++) {
            const int kk = ks * 16;
            uint32_t ah[2][4], al[2][4];
#pragma unroll
            for (int mt = 0; mt < 2; mt++) {
                int r0 = wm + mt * 16 + grp;
                ah[mt][0] = *(const uint32_t*)(Ah + (size_t)r0 * XS_ + kk + tig * 2);
                ah[mt][1] = *(const uint32_t*)(Ah + (size_t)(r0 + 8) * XS_ + kk + tig * 2);
                ah[mt][2] = *(const uint32_t*)(Ah + (size_t)r0 * XS_ + kk + 8 + tig * 2);
                ah[mt][3] = *(const uint32_t*)(Ah + (size_t)(r0 + 8) * XS_ + kk + 8 + tig * 2);
                al[mt][0] = *(const uint32_t*)(Al + (size_t)r0 * XS_ + kk + tig * 2);
                al[mt][1] = *(const uint32_t*)(Al + (size_t)(r0 + 8) * XS_ + kk + tig * 2);
                al[mt][2] = *(const uint32_t*)(Al + (size_t)r0 * XS_ + kk + 8 + tig * 2);
                al[mt][3] = *(const uint32_t*)(Al + (size_t)(r0 + 8) * XS_ + kk + 8 + tig * 2);
            }
#pragma unroll
            for (int nt = 0; nt < 8; nt++) {
                int nr = wn + nt * 8 + grp;
                uint32_t bh[2], bl[2];
                bh[0] = *(const uint32_t*)(Bh + (size_t)nr * XS_ + kk + tig * 2);
                bh[1] = *(const uint32_t*)(Bh + (size_t)nr * XS_ + kk + 8 + tig * 2);
                bl[0] = *(const uint32_t*)(Bl + (size_t)nr * XS_ + kk + tig * 2);
                bl[1] = *(const uint32_t*)(Bl + (size_t)nr * XS_ + kk + 8 + tig * 2);
#pragma unroll
                for (int mt = 0; mt < 2; mt++) {
                    mma_bf16(acc[mt][nt], ah[mt], bh);
                    mma_bf16(acc[mt][nt], ah[mt], bl);
                    mma_bf16(acc[mt][nt], al[mt], bh);
                }
            }
        }
        __syncthreads();
    }

#pragma unroll
    for (int mt = 0; mt < 2; mt++) {
#pragma unroll
        for (int nt = 0; nt < 8; nt++) {
            int row0 = bm + wm + mt * 16 + grp;
            int col = bn + wn + nt * 8 + tig * 2;
            *(float2*)(C + (size_t)row0 * H_ + col) =
                make_float2(acc[mt][nt][0], acc[mt][nt][1]);
            *(float2*)(C + (size_t)(row0 + 8) * H_ + col) =
                make_float2(acc[mt][nt][2], acc[mt][nt][3]);
        }
    }
}

// ---------------------------------------------------------------------------
// Gram -> mask + deg (round-10 proven, pre-split o3).
// ---------------------------------------------------------------------------
__global__ __launch_bounds__(256)
void gram_mma(const __nv_bfloat16* __restrict__ Xh,
              const __nv_bfloat16* __restrict__ Xl,
              unsigned char* __restrict__ mask,
              float* __restrict__ deg,
              const float* __restrict__ phi_p)
{
    int k = blockIdx.x;
    int bi = 0;
    while (k >= 64 - bi) { k -= 64 - bi; bi++; }
    const int bj = bi + k;
    const int bm = bi * 128;
    const int bn = bj * 128;

    extern __shared__ __align__(16) __nv_bfloat16 smr[];
    __nv_bfloat16* Ah = smr;
    __nv_bfloat16* Al = smr + 128 * XS_;
    __nv_bfloat16* Bh = smr + 2 * 128 * XS_;
    __nv_bfloat16* Bl = smr + 3 * 128 * XS_;

    const int tid = threadIdx.x;
    const int wid = tid >> 5;
    const int lane = tid & 31;
    const int wm = (wid & 3) * 32;
    const int wn = (wid >> 2) * 64;
    const int grp = lane >> 2;
    const int tig = lane & 3;

    float acc[2][8][4];
#pragma unroll
    for (int mt = 0; mt < 2; mt++)
#pragma unroll
        for (int nt = 0; nt < 8; nt++)
#pragma unroll
            for (int e = 0; e < 4; e++) acc[mt][nt][e] = 0.f;

    for (int kc = 0; kc < 4; kc++) {
#pragma unroll
        for (int i = 0; i < 8; i++) {
            int u = i * 256 + tid;
            int r = u >> 3;
            int cg = u & 7;
            int grow = (r < 128) ? (bm + r) : (bn + r - 128);
            int lr = r & 127;
            __nv_bfloat16* dh = (r < 128) ? Ah : Bh;
            __nv_bfloat16* dl = (r < 128) ? Al : Bl;
            size_t goff = (size_t)grow * H_ + kc * 64 + cg * 8;
            *(uint4*)(dh + lr * XS_ + cg * 8) = *(const uint4*)(Xh + goff);
            *(uint4*)(dl + lr * XS_ + cg * 8) = *(const uint4*)(Xl + goff);
        }
        __syncthreads();

#pragma unroll
        for (int ks = 0; ks < 4; ks++) {
            const int kk = ks * 16;
            uint32_t ah[2][4], al[2][4];
#pragma unroll
            for (int mt = 0; mt < 2; mt++) {
                int r0 = wm + mt * 16 + grp;
                ah[mt][0] = *(const uint32_t*)(Ah + (size_t)r0 * XS_ + kk + tig * 2);
                ah[mt][1] = *(const uint32_t*)(Ah + (size_t)(r0 + 8) * XS_ + kk + tig * 2);
                ah[mt][2] = *(const uint32_t*)(Ah + (size_t)r0 * XS_ + kk + 8 + tig * 2);
                ah[mt][3] = *(const uint32_t*)(Ah + (size_t)(r0 + 8) * XS_ + kk + 8 + tig * 2);
                al[mt][0] = *(const uint32_t*)(Al + (size_t)r0 * XS_ + kk + tig * 2);
                al[mt][1] = *(const uint32_t*)(Al + (size_t)(r0 + 8) * XS_ + kk + tig * 2);
                al[mt][2] = *(const uint32_t*)(Al + (size_t)r0 * XS_ + kk + 8 + tig * 2);
                al[mt][3] = *(const uint32_t*)(Al + (size_t)(r0 + 8) * XS_ + kk + 8 + tig * 2);
            }
#pragma unroll
            for (int nt = 0; nt < 8; nt++) {
                int nr = wn + nt * 8 + grp;
                uint32_t bh[2], bl[2];
                bh[0] = *(const uint32_t*)(Bh + (size_t)nr * XS_ + kk + tig * 2);
                bh[1] = *(const uint32_t*)(Bh + (size_t)nr * XS_ + kk + 8 + tig * 2);
                bl[0] = *(const uint32_t*)(Bl + (size_t)nr * XS_ + kk + tig * 2);
                bl[1] = *(const uint32_t*)(Bl + (size_t)nr * XS_ + kk + 8 + tig * 2);
#pragma unroll
                for (int mt = 0; mt < 2; mt++) {
                    mma_bf16(acc[mt][nt], ah[mt], bh);
                    mma_bf16(acc[mt][nt], ah[mt], bl);
                    mma_bf16(acc[mt][nt], al[mt], bh);
                }
            }
        }
        __syncthreads();
    }

    const float thr = phi_p[0] * 65536.0f;
    float cnt_r[2][2] = {{0.f, 0.f}, {0.f, 0.f}};
    float cnt_c[8][2];
#pragma unroll
    for (int nt = 0; nt < 8; nt++) { cnt_c[nt][0] = 0.f; cnt_c[nt][1] = 0.f; }
    unsigned bits[2][8];

#pragma unroll
    for (int mt = 0; mt < 2; mt++) {
        int r0 = bm + wm + mt * 16 + grp;
#pragma unroll
        for (int nt = 0; nt < 8; nt++) {
            int c0 = bn + wn + nt * 8 + tig * 2;
            unsigned b00 = (acc[mt][nt][0] >= thr || r0 == c0) ? 1u : 0u;
            unsigned b01 = (acc[mt][nt][1] >= thr || r0 == c0 + 1) ? 1u : 0u;
            unsigned b10 = (acc[mt][nt][2] >= thr || r0 + 8 == c0) ? 1u : 0u;
            unsigned b11 = (acc[mt][nt][3] >= thr || r0 + 8 == c0 + 1) ? 1u : 0u;
            *(unsigned short*)(mask + (size_t)r0 * NN_ + c0) =
                (unsigned short)(b00 | (b01 << 8));
            *(unsigned short*)(mask + (size_t)(r0 + 8) * NN_ + c0) =
                (unsigned short)(b10 | (b11 << 8));
            cnt_r[mt][0] += (float)(b00 + b01);
            cnt_r[mt][1] += (float)(b10 + b11);
            cnt_c[nt][0] += (float)(b00 + b10);
            cnt_c[nt][1] += (float)(b01 + b11);
            bits[mt][nt] = b00 | (b01 << 1) | (b10 << 2) | (b11 << 3);
        }
    }

#pragma unroll
    for (int mt = 0; mt < 2; mt++)
#pragma unroll
        for (int half = 0; half < 2; half++) {
            float v = cnt_r[mt][half];
            v += __shfl_xor_sync(0xffffffffu, v, 1);
            v += __shfl_xor_sync(0xffffffffu, v, 2);
            if (tig == 0)
                atomicAdd(&deg[bm + wm + mt * 16 + grp + half * 8], v);
        }

    if (bi != bj) {
#pragma unroll
        for (int nt = 0; nt < 8; nt++)
#pragma unroll
            for (int cb = 0; cb < 2; cb++) {
                float v = cnt_c[nt][cb];
                v += __shfl_xor_sync(0xffffffffu, v, 4);
                v += __shfl_xor_sync(0xffffffffu, v, 8);
                v += __shfl_xor_sync(0xffffffffu, v, 16);
                if (grp == 0)
                    atomicAdd(&deg[bn + wn + nt * 8 + tig * 2 + cb], v);
            }
#pragma unroll
        for (int nt = 0; nt < 8; nt++) {
            int c0 = bn + wn + nt * 8 + tig * 2;
#pragma unroll
            for (int cb = 0; cb < 2; cb++) {
                int col = c0 + cb;
#pragma unroll
                for (int mt = 0; mt < 2; mt++) {
                    int r0 = bm + wm + mt * 16 + grp;
                    mask[(size_t)col * NN_ + r0] =
                        (unsigned char)((bits[mt][nt] >> cb) & 1u);
                    mask[(size_t)col * NN_ + r0 + 8] =
                        (unsigned char)((bits[mt][nt] >> (2 + cb)) & 1u);
                }
            }
        }
    }
}

// ---------------------------------------------------------------------------
// Masked GCN GEMM (round-8 proven)
// ---------------------------------------------------------------------------
#define CS_ 72
__global__ __launch_bounds__(256, 2)
void gcn_gemm_mma(const unsigned char* __restrict__ mask,
                  const __nv_bfloat16* __restrict__ Yth,
                  const __nv_bfloat16* __restrict__ Ytl,
                  const float* __restrict__ dis,
                  const float* __restrict__ bias,
                  float* __restrict__ out)
{
    __shared__ __align__(16) __nv_bfloat16 Am[128 * CS_];
    __shared__ __align__(16) __nv_bfloat16 Bh[64 * CS_];
    __shared__ __align__(16) __nv_bfloat16 Bl[64 * CS_];

    const int bm = blockIdx.y * 128;
    const int bn = blockIdx.x * 64;
    const int tid = threadIdx.x;
    const int wid = tid >> 5;
    const int lane = tid & 31;
    const int wm = (wid & 3) * 32;
    const int wn = (wid >> 2) * 32;
    const int grp = lane >> 2;
    const int tig = lane & 3;

    float acc[2][4][4];
#pragma unroll
    for (int mt = 0; mt < 2; mt++)
#pragma unroll
        for (int nt = 0; nt < 4; nt++)
#pragma unroll
            for (int e = 0; e < 4; e++) acc[mt][nt][e] = 0.f;

    for (int kc = 0; kc < NN_ / 64; kc++) {
#pragma unroll
        for (int i = 0; i < 4; i++) {
            int u = i * 256 + tid;
            int r = u >> 3;
            int cg = u & 7;
            unsigned long long mb = *(const unsigned long long*)(
                mask + (size_t)(bm + r) * NN_ + kc * 64 + cg * 8);
            unsigned w[4];
#pragma unroll
            for (int p = 0; p < 4; p++) {
                unsigned lo16 = ((mb >> (16 * p)) & 0xFFull) ? 0x3F80u : 0u;
                unsigned hi16 = ((mb >> (16 * p + 8)) & 0xFFull) ? 0x3F80u : 0u;
                w[p] = lo16 | (hi16 << 16);
            }
            *(uint4*)(Am + r * CS_ + cg * 8) = make_uint4(w[0], w[1], w[2], w[3]);
        }
#pragma unroll
        for (int i = 0; i < 2; i++) {
            int u = i * 256 + tid;
            int r = u >> 3;
            int cg = u & 7;
            size_t goff = (size_t)(bn + r) * NN_ + kc * 64 + cg * 8;
            *(uint4*)(Bh + r * CS_ + cg * 8) = *(const uint4*)(Yth + goff);
            *(uint4*)(Bl + r * CS_ + cg * 8) = *(const uint4*)(Ytl + goff);
        }
        __syncthreads();

#pragma unroll
        for (int ks = 0; ks < 4; ks++) {
            const int kk = ks * 16;
            uint32_t am[2][4];
#pragma unroll
            for (int mt = 0; mt < 2; mt++) {
                int r0 = wm + mt * 16 + grp;
                am[mt][0] = *(const uint32_t*)(Am + (size_t)r0 * CS_ + kk + tig * 2);
                am[mt][1] = *(const uint32_t*)(Am + (size_t)(r0 + 8) * CS_ + kk + tig * 2);
                am[mt][2] = *(const uint32_t*)(Am + (size_t)r0 * CS_ + kk + 8 + tig * 2);
                am[mt][3] = *(const uint32_t*)(Am + (size_t)(r0 + 8) * CS_ + kk + 8 + tig * 2);
            }
#pragma unroll
            for (int nt = 0; nt < 4; nt++) {
                int nr = wn + nt * 8 + grp;
                uint32_t bh[2], bl[2];
                bh[0] = *(const uint32_t*)(Bh + (size_t)nr * CS_ + kk + tig * 2);
                bh[1] = *(const uint32_t*)(Bh + (size_t)nr * CS_ + kk + 8 + tig * 2);
                bl[0] = *(const uint32_t*)(Bl + (size_t)nr * CS_ + kk + tig * 2);
                bl[1] = *(const uint32_t*)(Bl + (size_t)nr * CS_ + kk + 8 + tig * 2);
#pragma unroll
                for (int mt = 0; mt < 2; mt++) {
                    mma_bf16(acc[mt][nt], am[mt], bh);
                    mma_bf16(acc[mt][nt], am[mt], bl);
                }
            }
        }
        __syncthreads();
    }

#pragma unroll
    for (int mt = 0; mt < 2; mt++) {
#pragma unroll
        for (int nt = 0; nt < 4; nt++) {
            int row0 = bm + wm + mt * 16 + grp;
            int col = bn + wn + nt * 8 + tig * 2;
            float2 bv = *(const float2*)(bias + col);
            float d0 = dis[row0];
            float d1 = dis[row0 + 8];
            float2 o0 = make_float2(d0 * acc[mt][nt][0] + bv.x,
                                    d0 * acc[mt][nt][1] + bv.y);
            float2 o1 = make_float2(d1 * acc[mt][nt][2] + bv.x,
                                    d1 * acc[mt][nt][3] + bv.y);
            *(float2*)(out + (size_t)row0 * GCN_ + col) = o0;
            *(float2*)(out + (size_t)(row0 + 8) * GCN_ + col) = o1;
        }
    }
}

// ---------------------------------------------------------------------------
// Sorting: rows by slen; nnz by edge and by node (fused setup kernels)
// ---------------------------------------------------------------------------
__global__ void setup_zero_kernel(int* __restrict__ hist, int* __restrict__ cur,
                                  int* __restrict__ ecnt, int* __restrict__ ecur,
                                  int* __restrict__ ncnt, int* __restrict__ ncur,
                                  float* __restrict__ deg)
{
    int i = blockIdx.x * 256 + threadIdx.x;
    if (i < 32) { hist[i] = 0; cur[i] = 0; }
    if (i < E_) { ecnt[i] = 0; ecur[i] = 0; }
    if (i < NN_) { ncnt[i] = 0; ncur[i] = 0; deg[i] = 0.f; }
}

__global__ void hist_kernel(const int* __restrict__ slen, int* __restrict__ hist)
{
    int i = blockIdx.x * 256 + threadIdx.x;
    if (i < NN_) atomicAdd(&hist[slen[i] - 1], 1);
}

__global__ void scan_kernel(const int* __restrict__ hist,
                            int* __restrict__ cnt, int* __restrict__ start)
{
    if (threadIdx.x == 0) {
        int run = 0;
        cnt[T_] = 0;
        for (int s = T_ - 1; s >= 0; s--) {
            start[s] = run;
            run += hist[s];
            cnt[s] = run;
        }
    }
}

__global__ void scatter_perm_kernel(const int* __restrict__ slen,
                                    const int* __restrict__ start,
                                    int* __restrict__ cur,
                                    int* __restrict__ perm)
{
    int i = blockIdx.x * 256 + threadIdx.x;
    if (i < NN_) {
        int s = slen[i] - 1;
        int pos = start[s] + atomicAdd(&cur[s], 1);
        perm[pos] = i;
    }
}

__global__ void hist_nz_kernel(const int* __restrict__ node_idx,
                               const int* __restrict__ edge_idx,
                               int* __restrict__ ncnt, int* __restrict__ ecnt)
{
    int i = blockIdx.x * 256 + threadIdx.x;
    if (i < NNZ_) {
        atomicAdd(&ncnt[node_idx[i]], 1);
        atomicAdd(&ecnt[edge_idx[i]], 1);
    }
}

__global__ void scan_bins_kernel(const int* __restrict__ cnt,
                                 int* __restrict__ off, int n)
{
    __shared__ int part[1024];
    int tid = threadIdx.x;
    int per = n / 1024;
    int base = tid * per;
    int s = 0;
    for (int i = 0; i < per; i++) s += cnt[base + i];
    part[tid] = s;
    __syncthreads();
    for (int d = 1; d < 1024; d <<= 1) {
        int v = (tid >= d) ? part[tid - d] : 0;
        __syncthreads();
        part[tid] += v;
        __syncthreads();
    }
    int run = part[tid] - s;
    for (int i = 0; i < per; i++) {
        off[base + i] = run;
        run += cnt[base + i];
    }
    if (tid == 1023) off[n] = run;
}

__global__ void scatter_orders_kernel(const int* __restrict__ node_idx,
                                      const int* __restrict__ edge_idx,
                                      const int* __restrict__ eoff,
                                      const int* __restrict__ noff,
                                      int* __restrict__ ecur,
                                      int* __restrict__ ncur,
                                      int* __restrict__ eorder,
                                      int* __restrict__ norder)
{
    int i = blockIdx.x * 256 + threadIdx.x;
    if (i < NNZ_) {
        int e = edge_idx[i];
        int pe = eoff[e] + atomicAdd(&ecur[e], 1);
        eorder[pe] = i;
        int n = node_idx[i];
        int pn = noff[n] + atomicAdd(&ncur[n], 1);
        norder[pn] = i;
    }
}

__global__ void inv_both_kernel(const int* __restrict__ ecnt,
                                const int* __restrict__ ncnt,
                                float* __restrict__ Binv,
                                float* __restrict__ Dinv)
{
    int i = blockIdx.x * 256 + threadIdx.x;
    if (i < E_) {
        int c = ecnt[i];
        Binv[i] = c > 0 ? 1.f / (float)c : 0.f;
    }
    if (i < NN_) {
        int c = ncnt[i];
        Dinv[i] = c > 0 ? 1.f / (float)c : 0.f;
    }
}

__global__ void init_h_kernel(float* __restrict__ h, const float* __restrict__ h0)
{
    int idx = blockIdx.x * 256 + threadIdx.x;
    h[idx] = h0[idx & (H_ - 1)];
}

// ---------------------------------------------------------------------------
// HGC segment sums (atomic-free)
// ---------------------------------------------------------------------------
__global__ void edge_sum_kernel(const float* __restrict__ xw,
                                const int* __restrict__ node_idx,
                                const int* __restrict__ eorder,
                                const int* __restrict__ eoff,
                                const float* __restrict__ Binv,
                                float* __restrict__ eb)
{
    int e = blockIdx.x;
    int c = threadIdx.x;
    int s0 = eoff[e], s1 = eoff[e + 1];
    float s = 0.f;
    for (int j = s0; j < s1; j++) {
        int nz = eorder[j];
        s += xw[(size_t)node_idx[nz] * H_ + c];
    }
    eb[(size_t)e * H_ + c] = s * Binv[e];
}

__global__ void node_sum_kernel(const float* __restrict__ eb,
                                const int* __restrict__ edge_idx,
                                const int* __restrict__ norder,
                                const int* __restrict__ noff,
                                const float* __restrict__ Dinv,
                                const float* __restrict__ bias,
                                const float* __restrict__ resid,
                                float* __restrict__ out)
{
    int n = blockIdx.x * 8 + (threadIdx.x >> 5);
    int lane = threadIdx.x & 31;
    int s0 = noff[n], s1 = noff[n + 1];
    float s[8];
#pragma unroll
    for (int k = 0; k < 8; k++) s[k] = 0.f;
    for (int j = s0; j < s1; j++) {
        int e = edge_idx[norder[j]];
        const float* er = eb + (size_t)e * H_;
#pragma unroll
        for (int k = 0; k < 8; k++) s[k] += er[lane + k * 32];
    }
    float di = Dinv[n];
#pragma unroll
    for (int k = 0; k < 8; k++) {
        int c = lane + k * 32;
        out[(size_t)n * H_ + c] = s[k] * di + bias[c] + resid[(size_t)n * H_ + c];
    }
}

__global__ void dis_kernel(const float* __restrict__ deg, float* __restrict__ dis)
{
    int i = blockIdx.x * 256 + threadIdx.x;
    if (i < NN_) {
        float d = deg[i];
        dis[i] = d > 0.f ? rsqrtf(d) : 0.f;
    }
}

// ---------------------------------------------------------------------------
// Host orchestration
// ---------------------------------------------------------------------------
extern "C" void kernel_launch(void* const* d_in, const int* in_sizes, int n_in,
                              void* d_out, int out_size)
{
    (void)in_sizes; (void)n_in; (void)out_size;

    const float* x        = (const float*)d_in[0];
    const int*   hei      = (const int*)d_in[1];
    const int*   node_idx = hei;
    const int*   edge_idx = hei + NNZ_;
    const int*   slen     = (const int*)d_in[2];
    const float* h0       = (const float*)d_in[3];
    const float* W_ih     = (const float*)d_in[4];
    const float* W_hh     = (const float*)d_in[5];
    const float* b_ih     = (const float*)d_in[6];
    const float* b_hh     = (const float*)d_in[7];
    const float* w1 = (const float*)d_in[8];  const float* bb1 = (const float*)d_in[9];
    const float* w2 = (const float*)d_in[10]; const float* bb2 = (const float*)d_in[11];
    const float* w3 = (const float*)d_in[12]; const float* bb3 = (const float*)d_in[13];
    const float* phi = (const float*)d_in[14];
    const float* gw  = (const float*)d_in[15];
    const float* gb  = (const float*)d_in[16];
    float* out = (float*)d_out;

    float *xgall, *h, *h2, *fa, *fb, *xw, *eb, *x2, *deg, *Dinv, *Binv, *dis;
    unsigned char* mask;
    __nv_bfloat16 *whh_h, *whh_l, *wih_h, *wih_l, *o3h, *o3l, *yth, *ytl, *wt_h, *wt_l;
    int *perm, *histb, *curb, *startb, *cntb;
    int *ecnt, *ncnt, *ecur, *ncur, *eoff, *noff, *eorder, *norder;
    cudaGetSymbolAddress((void**)&xgall, g_xgall);
    cudaGetSymbolAddress((void**)&h,     g_h);
    cudaGetSymbolAddress((void**)&h2,    g_h2);
    cudaGetSymbolAddress((void**)&fa,    g_fa);
    cudaGetSymbolAddress((void**)&fb,    g_fb);
    cudaGetSymbolAddress((void**)&xw,    g_xw);
    cudaGetSymbolAddress((void**)&eb,    g_eb);
    cudaGetSymbolAddress((void**)&x2,    g_x2);
    cudaGetSymbolAddress((void**)&mask,  g_mask);
    cudaGetSymbolAddress((void**)&deg,   g_deg);
    cudaGetSymbolAddress((void**)&Dinv,  g_Dinv);
    cudaGetSymbolAddress((void**)&Binv,  g_Binv);
    cudaGetSymbolAddress((void**)&dis,   g_dis);
    cudaGetSymbolAddress((void**)&whh_h, g_whh_h);
    cudaGetSymbolAddress((void**)&whh_l, g_whh_l);
    cudaGetSymbolAddress((void**)&wih_h, g_wih_h);
    cudaGetSymbolAddress((void**)&wih_l, g_wih_l);
    cudaGetSymbolAddress((void**)&o3h,   g_o3h);
    cudaGetSymbolAddress((void**)&o3l,   g_o3l);
    cudaGetSymbolAddress((void**)&yth,   g_yth);
    cudaGetSymbolAddress((void**)&ytl,   g_ytl);
    cudaGetSymbolAddress((void**)&wt_h,  g_wt_h);
    cudaGetSymbolAddress((void**)&wt_l,  g_wt_l);
    cudaGetSymbolAddress((void**)&perm,  g_perm);
    cudaGetSymbolAddress((void**)&histb, g_hist);
    cudaGetSymbolAddress((void**)&curb,  g_cur);
    cudaGetSymbolAddress((void**)&startb,g_start);
    cudaGetSymbolAddress((void**)&cntb,  g_cnt);
    cudaGetSymbolAddress((void**)&ecnt,  g_ecnt);
    cudaGetSymbolAddress((void**)&ncnt,  g_ncnt);
    cudaGetSymbolAddress((void**)&ecur,  g_ecur);
    cudaGetSymbolAddress((void**)&ncur,  g_ncur);
    cudaGetSymbolAddress((void**)&eoff,  g_eoff);
    cudaGetSymbolAddress((void**)&noff,  g_noff);
    cudaGetSymbolAddress((void**)&eorder,g_eorder);
    cudaGetSymbolAddress((void**)&norder,g_norder);

    const int XG_SMEM  = 4 * 128 * XS_ * 2;                  // 90112 B
    const int GRU_SMEM = (2 * 64 * GS_ + 2 * 192 * GS_) * 2; // 73728 B
    cudaFuncSetAttribute(xg_gemm_mma,
                         cudaFuncAttributeMaxDynamicSharedMemorySize, XG_SMEM);
    cudaFuncSetAttribute(gru_step_mma,
                         cudaFuncAttributeMaxDynamicSharedMemorySize, GRU_SMEM);
    cudaFuncSetAttribute(sgemm_nt_mma,
                         cudaFuncAttributeMaxDynamicSharedMemorySize, XG_SMEM);
    cudaFuncSetAttribute(gram_mma,
                         cudaFuncAttributeMaxDynamicSharedMemorySize, XG_SMEM);

    // ---------------- fused setup ----------------
    setup_zero_kernel<<<NN_ / 256, 256>>>(histb, curb, ecnt, ecur, ncnt, ncur, deg);
    hist_kernel<<<NN_ / 256, 256>>>(slen, histb);
    scan_kernel<<<1, 32>>>(histb, cntb, startb);
    scatter_perm_kernel<<<NN_ / 256, 256>>>(slen, startb, curb, perm);

    hist_nz_kernel<<<NNZ_ / 256, 256>>>(node_idx, edge_idx, ncnt, ecnt);
    scan_bins_kernel<<<1, 1024>>>(ecnt, eoff, E_);
    scan_bins_kernel<<<1, 1024>>>(ncnt, noff, NN_);
    scatter_orders_kernel<<<NNZ_ / 256, 256>>>(node_idx, edge_idx, eoff, noff,
                                               ecur, ncur, eorder, norder);
    inv_both_kernel<<<NN_ / 256, 256>>>(ecnt, ncnt, Binv, Dinv);

    // ---------------- one-time weight splits ----------------
    split_w_kernel<<<(H3_ * H_ + 255) / 256, 256>>>(W_hh, whh_h, whh_l, H3_ * H_);
    split_w_kernel<<<(H3_ * IN_ + 255) / 256, 256>>>(W_ih, wih_h, wih_l, H3_ * IN_);
    wt_split_kernel<<<dim3(8, 8), dim3(32, 8)>>>(w1, wt_h, wt_l);
    wt_split_kernel<<<dim3(8, 8), dim3(32, 8)>>>(w2, wt_h + H_ * H_, wt_l + H_ * H_);
    wt_split_kernel<<<dim3(8, 8), dim3(32, 8)>>>(w3, wt_h + 2 * H_ * H_, wt_l + 2 * H_ * H_);
    wt_split_kernel<<<dim3(8, 8), dim3(32, 8)>>>(gw, wt_h + 3 * H_ * H_, wt_l + 3 * H_ * H_);

    // ---------------- GRU ----------------
    init_h_kernel<<<NN_ * H_ / 256, 256>>>(h, h0);
    xg_gemm_mma<<<dim3(H3_ / 128, T_ * NN_ / 128), 256, XG_SMEM>>>(
        x, wih_h, wih_l, b_ih, perm, cntb, xgall);

    float* hrd = h;
    float* hwr = h2;
    for (int t = 0; t < T_; t++) {
        gru_step_mma<<<dim3(H_ / 64, NN_ / 64), 256, GRU_SMEM>>>(
            whh_h, whh_l, b_hh, xgall, hrd, hwr, perm, cntb, fa, t);
        float* tmp = hrd; hrd = hwr; hwr = tmp;
    }
    // fa holds `last` in original row order

    // ---------------- 3 hypergraph conv layers (atomic-free) ----------------
    const float* hgc_in[3]  = {fa, fb, fa};
    float*       hgc_out[3] = {fb, fa, fb};
    const float* hgc_b[3]   = {bb1, bb2, bb3};
    for (int l = 0; l < 3; l++) {
        sgemm_nt_mma<<<dim3(2, NN_ / 128), 256, XG_SMEM>>>(
            hgc_in[l], wt_h + l * H_ * H_, wt_l + l * H_ * H_, xw);
        edge_sum_kernel<<<E_, 256>>>(xw, node_idx, eorder, eoff, Binv, eb);
        node_sum_kernel<<<NN_ / 8, 256>>>(eb, edge_idx, norder, noff, Dinv,
                                          hgc_b[l], hgc_in[l], hgc_out[l]);
    }
    // fb holds o3

    // ---------------- final dense GCN ----------------
    sgemm_nt_mma<<<dim3(2, NN_ / 128), 256, XG_SMEM>>>(
        fb, wt_h + 3 * H_ * H_, wt_l + 3 * H_ * H_, x2);

    split_w_kernel<<<(NN_ * H_ + 255) / 256, 256>>>(fb, o3h, o3l, NN_ * H_);
    gram_mma<<<64 * 65 / 2, 256, XG_SMEM>>>(o3h, o3l, mask, deg, phi);
    dis_kernel<<<(NN_ + 255) / 256, 256>>>(deg, dis);
    yt_split_kernel<<<dim3(NN_ / 32, GCN_ / 32), dim3(32, 8)>>>(x2, dis, yth, ytl);
    gcn_gemm_mma<<<dim3(GCN_ / 64, NN_ / 128), 256>>>(mask, yth, ytl, dis, gb, out);
}